// round 14
// baseline (speedup 1.0000x reference)
#include <cuda_runtime.h>
#include <cuda_fp16.h>
#include <math.h>
#include <stdint.h>

// Problem constants
#define BB 4
#define SS 1024
#define DD 1024
#define HH 16
#define DKK 64
#define DFFF 4096
#define SCP 1032   // score row pitch (floats)

// ---------------- scratch (device globals) -----------------------------------
__device__ float g_attnout[BB*SS*DD];
__device__ float g_x[BB*SS*DD];
__device__ float g_f[BB*SS*DD];
__device__ __half g_aq[BB*SS*DD];
__device__ __half g_ak[BB*SS*DD];
__device__ __half g_av[BB*SS*DD];
__device__ __half g_wq_h[DD*DD];
__device__ __half g_wk_h[DD*DD];
__device__ __half g_wv_h[DD*DD];
__device__ __half g_wo_h[DD*DD];
__device__ __half g_w1_h[DFFF*DD];
__device__ __half g_w2_h[DD*DFFF];
__device__ __half g_chi[BB*SS*DD];
__device__ __half g_xh[BB*SS*DD];
__device__ __half g_hh[BB*SS*DFFF];
__device__ __half g_qhi[BB*SS*DD], g_qlo[BB*SS*DD];
__device__ __half g_khi[BB*SS*DD];
__device__ __half g_vhi[BB*SS*DD];

// ======================= PTX helpers ========================================
__device__ __forceinline__ uint32_t smem_u32(const void* p) {
    uint32_t a;
    asm("{ .reg .u64 t; cvta.to.shared.u64 t, %1; cvt.u32.u64 %0, t; }" : "=r"(a) : "l"(p));
    return a;
}

#define CPASYNC16(dst, src) asm volatile("cp.async.cg.shared.global [%0], [%1], 16;" :: "r"(dst), "l"(src) : "memory")
#define CPCOMMIT() asm volatile("cp.async.commit_group;" ::: "memory")
#define CPWAIT1()  asm volatile("cp.async.wait_group 1;" ::: "memory")
#define CPWAIT0()  asm volatile("cp.async.wait_group 0;" ::: "memory")

#define LDSM_X4(R, A) \
    asm volatile("ldmatrix.sync.aligned.m8n8.x4.shared.b16 {%0,%1,%2,%3}, [%4];" \
        : "=r"((R)[0]), "=r"((R)[1]), "=r"((R)[2]), "=r"((R)[3]) : "r"(A))

#define LDSM_X2T(R, A) \
    asm volatile("ldmatrix.sync.aligned.m8n8.x2.trans.shared.b16 {%0,%1}, [%2];" \
        : "=r"((R)[0]), "=r"((R)[1]) : "r"(A))

__device__ __forceinline__ void mma_f16(float* c, const uint32_t* a, const uint32_t* b) {
    asm volatile(
        "mma.sync.aligned.m16n8k16.row.col.f32.f16.f16.f32 "
        "{%0,%1,%2,%3}, {%4,%5,%6,%7}, {%8,%9}, {%0,%1,%2,%3};"
        : "+f"(c[0]), "+f"(c[1]), "+f"(c[2]), "+f"(c[3])
        : "r"(a[0]), "r"(a[1]), "r"(a[2]), "r"(a[3]), "r"(b[0]), "r"(b[1]));
}

__device__ __forceinline__ uint32_t packh2(float x, float y) {
    __half2 t = __floats2half2_rn(x, y);
    return *reinterpret_cast<uint32_t*>(&t);
}
__device__ __forceinline__ uint32_t packloh2(float x, float y, uint32_t hi) {
    __half2 h = *reinterpret_cast<__half2*>(&hi);
    return packh2(x - __half2float(h.x), y - __half2float(h.y));
}

// ================ mega split: fp32 -> single fp16 ===========================
struct SplitSeg { const float* src; __half* hi; };
struct SplitArgs { SplitSeg seg[9]; int start[10]; };

__global__ void __launch_bounds__(256) multi_split_kernel(SplitArgs a)
{
    int bx = blockIdx.x;
    int s = 0;
#pragma unroll
    for (int i = 0; i < 8; i++) if (bx >= a.start[i+1]) s = i+1;
    SplitSeg sg = a.seg[s];
    int i = (bx - a.start[s]) * 256 + threadIdx.x;
    float4 v = ((const float4*)sg.src)[i];
    uint32_t h0 = packh2(v.x, v.y), h1 = packh2(v.z, v.w);
    ((uint32_t*)sg.hi)[i*2+0] = h0;
    ((uint32_t*)sg.hi)[i*2+1] = h1;
}

// ====== fp16 GEMM: C = A @ W^T + bias, tile 256x128, K-chunk 64, 3 stages ===
#define G_BH 36864
#define G_STAGE 55296
#define G_SMEM (3 * G_STAGE)   // 165888

struct GemmIO {
    const __half *Ah, *Wh;
    const float* bias;
    float* C;
    __half *Chi, *Clo;   // Clo may be null
};

template<bool RELU, bool SPLITOUT>
__global__ void __launch_bounds__(512, 1) gemm_mma(
    GemmIO io0, GemmIO io1, GemmIO io2, int M, int N, int K)
{
    extern __shared__ __align__(128) char smem[];
    uint32_t sb = smem_u32(smem);

    GemmIO io = (blockIdx.z == 0) ? io0 : (blockIdx.z == 1) ? io1 : io2;

    int tid  = threadIdx.x;
    int lane = tid & 31;
    int wid  = tid >> 5;
    int wm   = wid & 3;
    int wn   = wid >> 2;
    int bm = blockIdx.y * 256;
    int bn = blockIdx.x * 128;

    const int nch = K >> 6;

    auto load_stage = [&](int c) {
        uint32_t st = sb + (c % 3) * G_STAGE;
        size_t kof = (size_t)c * 64;
        const __half* a_h = io.Ah + (size_t)bm * K + kof;
        const __half* b_h = io.Wh + (size_t)bn * K + kof;
#pragma unroll
        for (int u = 0; u < 4; u++) {
            int l = tid + u * 512;
            int row = l >> 3, ch = l & 7;
            CPASYNC16(st + row*144 + ch*16, (const char*)(a_h + (size_t)row*K) + ch*16);
        }
#pragma unroll
        for (int u = 0; u < 2; u++) {
            int l = tid + u * 512;
            int row = l >> 3, ch = l & 7;
            CPASYNC16(st + G_BH + row*144 + ch*16, (const char*)(b_h + (size_t)row*K) + ch*16);
        }
        CPCOMMIT();
    };

    uint32_t aoff = ((((lane >> 3) & 1) * 8 + (lane & 7)) * 144) + (lane >> 4) * 16;
    uint32_t boff = (((lane >> 4) * 8 + (lane & 7)) * 144) + ((lane >> 3) & 1) * 16;

    float acc[4][4][4];
#pragma unroll
    for (int mt = 0; mt < 4; mt++)
#pragma unroll
        for (int n8 = 0; n8 < 4; n8++)
#pragma unroll
            for (int k = 0; k < 4; k++) acc[mt][n8][k] = 0.f;

    load_stage(0);
    load_stage(1);
    for (int c = 0; c < nch; c++) {
        if (c + 1 < nch) { CPWAIT1(); } else { CPWAIT0(); }
        __syncthreads();
        if (c + 2 < nch) load_stage(c + 2);

        uint32_t st = sb + (c % 3) * G_STAGE;
        uint32_t aH = st        + (wm * 64) * 144 + aoff;
        uint32_t bH = st + G_BH + (wn * 32) * 144 + boff;

#pragma unroll
        for (int ks = 0; ks < 4; ks++) {
            uint32_t ah[4][4];
#pragma unroll
            for (int mt = 0; mt < 4; mt++)
                LDSM_X4(ah[mt], aH + mt * (16*144) + ks * 32);
#pragma unroll
            for (int g = 0; g < 2; g++) {
                uint32_t bh[4];
                LDSM_X4(bh, bH + g * (16*144) + ks * 32);
#pragma unroll
                for (int mt = 0; mt < 4; mt++)
#pragma unroll
                    for (int hf = 0; hf < 2; hf++)
                        mma_f16(acc[mt][g*2+hf], ah[mt], &bh[hf*2]);
            }
        }
    }

    int r_in = lane >> 2;
    int c_in = (lane & 3) * 2;
    bool wlo = SPLITOUT && (io.Clo != nullptr);
#pragma unroll
    for (int mt = 0; mt < 4; mt++) {
        int R0 = bm + wm * 64 + mt * 16 + r_in;
        int R1 = R0 + 8;
#pragma unroll
        for (int n8 = 0; n8 < 4; n8++) {
            int col = bn + wn * 32 + n8 * 8 + c_in;
            float b0 = io.bias[col], b1 = io.bias[col + 1];
            float o00 = acc[mt][n8][0] + b0, o01 = acc[mt][n8][1] + b1;
            float o10 = acc[mt][n8][2] + b0, o11 = acc[mt][n8][3] + b1;
            if (RELU) {
                o00 = fmaxf(o00, 0.f); o01 = fmaxf(o01, 0.f);
                o10 = fmaxf(o10, 0.f); o11 = fmaxf(o11, 0.f);
            }
            if (SPLITOUT) {
                uint32_t h0 = packh2(o00, o01), h1 = packh2(o10, o11);
                *(uint32_t*)&io.Chi[(size_t)R0 * N + col] = h0;
                *(uint32_t*)&io.Chi[(size_t)R1 * N + col] = h1;
                if (wlo) {
                    uint32_t l0 = packloh2(o00, o01, h0), l1 = packloh2(o10, o11, h1);
                    *(uint32_t*)&io.Clo[(size_t)R0 * N + col] = l0;
                    *(uint32_t*)&io.Clo[(size_t)R1 * N + col] = l1;
                }
            } else {
                float2 o0, o1;
                o0.x = o00; o0.y = o01; o1.x = o10; o1.y = o11;
                *(float2*)&io.C[(size_t)R0 * N + col] = o0;
                *(float2*)&io.C[(size_t)R1 * N + col] = o1;
            }
        }
    }
}

// ================= tensor-core distance-decay attention ======================
// 256 threads (8 warps), 16 rows/CTA, 2 CTAs/SM (smem 107.5 KB).
// Grid (64, 64): x = h + 16*b, y = i0 tile (wave-balanced).
// QK: 2-term (q hi/lo x k hi). PV: probs hi/lo x V single.
#define AT_QH 66048
#define AT_QL (AT_QH + 2304)
#define AT_K  (AT_QL + 2304)
#define AT_KSZ 18432     // 128 rows x 144B per buffer
#define AT_SMEM (AT_K + 2*AT_KSZ)   // 107520

__global__ void __launch_bounds__(256, 2) attn_kernel(
    const __half* __restrict__ qhi, const __half* __restrict__ qlo,
    const __half* __restrict__ khi, const __half* __restrict__ vhi,
    const float* __restrict__ gammas,
    __half* __restrict__ ohi)
{
    extern __shared__ __align__(128) char smx[];
    float* sc = (float*)smx;
    uint32_t sb = smem_u32(smx);
    const uint32_t QH = sb + AT_QH;
    const uint32_t QL = sb + AT_QL;

    int h = blockIdx.x & 15, b = blockIdx.x >> 4;
    int i0 = blockIdx.y * 16;
    int t = threadIdx.x, lane = t & 31, w = t >> 5;   // w: 0..7

    size_t base_q = ((size_t)b*SS + i0)*DD + h*64;
    size_t base_k = (size_t)b*SS*DD + h*64;

    // ---- load Q tile (16 rows, hi+lo): 256 chunks = 1/thread
    {
        int sel = t >> 7;
        int idx = t & 127;
        int row = idx >> 3, ch = idx & 7;
        const __half* src = (sel ? qlo : qhi) + base_q + (size_t)row*DD + ch*8;
        char* dst = smx + (sel ? AT_QL : AT_QH) + row*144 + ch*16;
        *(float4*)dst = *(const float4*)src;
    }
    __syncthreads();

    uint32_t aoff = ((((lane >> 3) & 1) * 8 + (lane & 7)) * 144) + (lane >> 4) * 16;
    uint32_t boff = (((lane >> 4) * 8 + (lane & 7)) * 144) + ((lane >> 3) & 1) * 16;

    uint32_t ah[4][4], al[4][4];
#pragma unroll
    for (int ks = 0; ks < 4; ks++) {
        LDSM_X4(ah[ks], QH + aoff + ks*32);
        LDSM_X4(al[ks], QL + aoff + ks*32);
    }

    // K tile loader (128 rows) into buffer bf: 1024 chunks / 256 thr = 4 iters
    auto loadK = [&](int jt, int bf) {
        uint32_t KH = sb + AT_K + bf * AT_KSZ;
        int jbase = jt * 128;
#pragma unroll
        for (int u = 0; u < 4; u++) {
            int l = t + u * 256;
            int row = l >> 3, ch = l & 7;
            const char* sh = (const char*)(khi + base_k + (size_t)(jbase+row)*DD) + ch*16;
            CPASYNC16(KH + row*144 + ch*16, sh);
        }
        CPCOMMIT();
    };

    // ---- QK^T: 8 tiles of 128 cols, double-buffered
    loadK(0, 0);
    for (int jt = 0; jt < 8; jt++) {
        CPWAIT0();
        __syncthreads();
        if (jt + 1 < 8) loadK(jt + 1, (jt + 1) & 1);

        uint32_t KH = sb + AT_K + (jt & 1) * AT_KSZ;
        float c0[4] = {0,0,0,0}, c1[4] = {0,0,0,0};
        uint32_t bb = (uint32_t)(w*16)*144 + boff;
#pragma unroll
        for (int ks = 0; ks < 4; ks++) {
            uint32_t bh[4];
            LDSM_X4(bh, KH + bb + ks*32);
            mma_f16(c0, ah[ks], &bh[0]);
            mma_f16(c0, al[ks], &bh[0]);
            mma_f16(c1, ah[ks], &bh[2]);
            mma_f16(c1, al[ks], &bh[2]);
        }
        int r0 = lane >> 2;
        int cb = jt*128 + w*16 + (lane & 3)*2;
        float2 v2;
        v2.x = c0[0]*0.125f; v2.y = c0[1]*0.125f; *(float2*)&sc[r0*SCP + cb] = v2;
        v2.x = c0[2]*0.125f; v2.y = c0[3]*0.125f; *(float2*)&sc[(r0+8)*SCP + cb] = v2;
        v2.x = c1[0]*0.125f; v2.y = c1[1]*0.125f; *(float2*)&sc[r0*SCP + cb + 8] = v2;
        v2.x = c1[2]*0.125f; v2.y = c1[3]*0.125f; *(float2*)&sc[(r0+8)*SCP + cb + 8] = v2;
    }

    int jmax = i0 + 16;
    auto loadV = [&](int jbase, int rows, int bf) {
        uint32_t VH = sb + AT_K + bf * AT_KSZ;
        int total = rows * 8;
#pragma unroll
        for (int u = 0; u < 4; u++) {
            int l = t + u * 256;
            if (l < total) {
                int row = l >> 3, ch = l & 7;
                const char* sh = (const char*)(vhi + base_k + (size_t)(jbase+row)*DD) + ch*16;
                CPASYNC16(VH + row*144 + ch*16, sh);
            }
        }
        CPCOMMIT();
    };

    // prefetch V tile 0 into buffer 0 (jt=7 used buffer 1) — hidden under row math
    loadV(0, jmax < 128 ? jmax : 128, 0);
    __syncthreads();   // sc writes visible before row math

    // ---- per-row math: 2 rows per warp, array-free, pass-C unrolled x2
    {
        float gamma = -log1pf(__expf(gammas[h]));
        for (int rr2 = 0; rr2 < 2; rr2++) {
            int r  = w*2 + rr2;
            int ig = i0 + r;
            float* row = sc + r*SCP;
            int cmask = ig >> 5;

            // pass A: row max
            float m = -INFINITY;
            for (int c = 0; c < 32; c++) m = fmaxf(m, row[c*32 + lane]);
#pragma unroll
            for (int o = 16; o > 0; o >>= 1) m = fmaxf(m, __shfl_xor_sync(0xffffffffu, m, o));

            // pass B: sums
            float sum1 = 0.f, summ = 0.f;
            for (int c = 0; c < 32; c++) {
                int j = c*32 + lane;
                float pfull = __expf(row[j] - m);
                sum1 += pfull;
                if (j <= ig) summ += pfull;
            }
#pragma unroll
            for (int o = 16; o > 0; o >>= 1) {
                sum1 += __shfl_xor_sync(0xffffffffu, sum1, o);
                summ += __shfl_xor_sync(0xffffffffu, summ, o);
            }
            float inv1 = 1.f / sum1;

            // pass C: fused scan + decay, 2 chunks/iter (independent scans)
            float carry = 0.f, m2 = -INFINITY;
            for (int c = 0; c <= cmask; c += 2) {
                int j0 = c*32 + lane;
                int j1 = j0 + 32;
                bool has1 = (c + 1 <= cmask);
                float s0 = row[j0];
                float s1v = has1 ? row[j1] : -INFINITY;
                float x0 = (j0 <= ig) ? __expf(s0 - m) : 0.f;
                float x1 = (has1 && j1 <= ig) ? __expf(s1v - m) : 0.f;
#pragma unroll
                for (int o = 1; o < 32; o <<= 1) {
                    float y0 = __shfl_up_sync(0xffffffffu, x0, o);
                    float y1 = __shfl_up_sync(0xffffffffu, x1, o);
                    if (lane >= o) { x0 += y0; x1 += y1; }
                }
                float t0 = __shfl_sync(0xffffffffu, x0, 31);
                float t1 = __shfl_sync(0xffffffffu, x1, 31);
                float d0 = carry + x0;
                float d1 = carry + t0 + x1;
                carry += t0 + t1;
                {
                    float pos  = fabsf((float)(ig - j0));
                    float dd   = (summ - d0) * inv1 * pos;
                    float dist = sqrtf(fmaxf(dd, 0.f));
                    float eff  = fminf(fmaxf(__expf(dist * gamma), 1e-5f), 1e5f);
                    float s2 = (j0 <= ig) ? s0 * eff : -INFINITY;
                    row[j0] = s2;
                    m2 = fmaxf(m2, s2);
                }
                if (has1) {
                    float pos  = fabsf((float)(ig - j1));
                    float dd   = (summ - d1) * inv1 * pos;
                    float dist = sqrtf(fmaxf(dd, 0.f));
                    float eff  = fminf(fmaxf(__expf(dist * gamma), 1e-5f), 1e5f);
                    float s2 = (j1 <= ig) ? s1v * eff : -INFINITY;
                    row[j1] = s2;
                    m2 = fmaxf(m2, s2);
                }
            }
#pragma unroll
            for (int o = 16; o > 0; o >>= 1) m2 = fmaxf(m2, __shfl_xor_sync(0xffffffffu, m2, o));

            // pass D: sum2
            float sum2 = 0.f;
            for (int c = 0; c <= cmask; c++) {
                int j = c*32 + lane;
                sum2 += (j <= ig) ? __expf(row[j] - m2) : 0.f;
            }
#pragma unroll
            for (int o = 16; o > 0; o >>= 1) sum2 += __shfl_xor_sync(0xffffffffu, sum2, o);
            float inv2 = 1.f / sum2;

            // pass E: final probs; zero tail up to jmax
            int clim = (jmax + 31) >> 5;
            for (int c = 0; c < clim; c++) {
                int j = c*32 + lane;
                float val = 0.f;
                if (c <= cmask && j <= ig) val = __expf(row[j] - m2) * inv2;
                row[j] = val;
            }
        }
    }

    // ---- PV: warp w -> cols w*8..w*8+7, all 16 rows
    float acc[4] = {0.f, 0.f, 0.f, 0.f};
    int rr = lane >> 2, kc = (lane & 3) * 2;
    int vrow = lane & 15;
    int ntiles = (jmax + 127) >> 7;
    for (int ji = 0; ji < ntiles; ji++) {
        int jbase = ji * 128;
        int rows = jmax - jbase; if (rows > 128) rows = 128;
        CPWAIT0();
        __syncthreads();
        if (ji + 1 < ntiles) {
            int nb = jbase + 128;
            int nrows = jmax - nb; if (nrows > 128) nrows = 128;
            loadV(nb, nrows, (ji + 1) & 1);
        }
        uint32_t VH = sb + AT_K + (ji & 1) * AT_KSZ;

        int nk = rows >> 4;
        for (int kk = 0; kk < nk; kk++) {
            int j0 = jbase + kk*16;
            uint32_t vh[2];
            uint32_t va = (uint32_t)(kk*16 + vrow)*144 + (uint32_t)w*16;
            LDSM_X2T(vh, VH + va);
            const float* p0 = &sc[rr*SCP + j0 + kc];
            float f00 = p0[0],        f01 = p0[1];
            float f10 = p0[8*SCP],    f11 = p0[8*SCP+1];
            float f20 = p0[8],        f21 = p0[9];
            float f30 = p0[8*SCP+8],  f31 = p0[8*SCP+9];
            uint32_t a_h[4], a_l[4];
            a_h[0] = packh2(f00, f01); a_l[0] = packloh2(f00, f01, a_h[0]);
            a_h[1] = packh2(f10, f11); a_l[1] = packloh2(f10, f11, a_h[1]);
            a_h[2] = packh2(f20, f21); a_l[2] = packloh2(f20, f21, a_h[2]);
            a_h[3] = packh2(f30, f31); a_l[3] = packloh2(f30, f31, a_h[3]);
            mma_f16(acc, a_h, vh);
            mma_f16(acc, a_l, vh);
        }
    }

    // ---- epilogue -> concat single fp16
    {
        size_t o0 = ((size_t)b*SS + i0 + rr)*DD + h*64 + w*8 + kc;
        size_t o1 = o0 + (size_t)8*DD;
        *(uint32_t*)&ohi[o0] = packh2(acc[0], acc[1]);
        *(uint32_t*)&ohi[o1] = packh2(acc[2], acc[3]);
    }
}

// ---------------- residual add + LayerNorm ----------------------------------
template<bool SPLITOUT>
__global__ void __launch_bounds__(256) add_ln_kernel(
    const float* __restrict__ A, const float* __restrict__ Bres,
    const float* __restrict__ w, const float* __restrict__ bias,
    float* __restrict__ outp,
    __half* __restrict__ ohi)
{
    __shared__ float red1[8], red2[8];
    int row = blockIdx.x;
    int t   = threadIdx.x;
    const float* pa = A    + (size_t)row*DD;
    const float* pb = Bres + (size_t)row*DD;

    float4 a4 = *(const float4*)&pa[t*4];
    float4 b4 = *(const float4*)&pb[t*4];
    float v0 = a4.x + b4.x, v1 = a4.y + b4.y, v2 = a4.z + b4.z, v3 = a4.w + b4.w;

    int lane = t & 31, wp = t >> 5;
    float s = v0 + v1 + v2 + v3;
#pragma unroll
    for (int o = 16; o > 0; o >>= 1) s += __shfl_xor_sync(0xffffffffu, s, o);
    if (lane == 0) red1[wp] = s;
    __syncthreads();
    float tot = 0.f;
#pragma unroll
    for (int i = 0; i < 8; i++) tot += red1[i];
    float mu = tot * (1.f / DD);

    float d0 = v0-mu, d1 = v1-mu, d2 = v2-mu, d3 = v3-mu;
    float q2 = d0*d0 + d1*d1 + d2*d2 + d3*d3;
#pragma unroll
    for (int o = 16; o > 0; o >>= 1) q2 += __shfl_xor_sync(0xffffffffu, q2, o);
    if (lane == 0) red2[wp] = q2;
    __syncthreads();
    float tv = 0.f;
#pragma unroll
    for (int i = 0; i < 8; i++) tv += red2[i];
    float inv = rsqrtf(tv * (1.f / DD) + 1e-5f);

    float4 w4  = *(const float4*)&w[t*4];
    float4 bi4 = *(const float4*)&bias[t*4];
    float4 o4;
    o4.x = d0*inv*w4.x + bi4.x;
    o4.y = d1*inv*w4.y + bi4.y;
    o4.z = d2*inv*w4.z + bi4.z;
    o4.w = d3*inv*w4.w + bi4.w;
    *(float4*)&outp[(size_t)row*DD + t*4] = o4;

    if (SPLITOUT) {
        uint32_t h0 = packh2(o4.x, o4.y), h1 = packh2(o4.z, o4.w);
        size_t base2 = (size_t)row * (DD/2) + t*2;
        ((uint32_t*)ohi)[base2]     = h0;
        ((uint32_t*)ohi)[base2 + 1] = h1;
    }
}

// ---------------- launcher ---------------------------------------------------
extern "C" void kernel_launch(void* const* d_in, const int* in_sizes, int n_in,
                              void* d_out, int out_size)
{
    int off = (in_sizes[0] == 1) ? 1 : 0;
    const float* query  = (const float*)d_in[off + 0];
    const float* key    = (const float*)d_in[off + 1];
    const float* values = (const float*)d_in[off + 2];
    const float* Wq = (const float*)d_in[off + 3];
    const float* bq = (const float*)d_in[off + 4];
    const float* Wk = (const float*)d_in[off + 5];
    const float* bk = (const float*)d_in[off + 6];
    const float* Wv = (const float*)d_in[off + 7];
    const float* bv = (const float*)d_in[off + 8];
    const float* Wo = (const float*)d_in[off + 9];
    const float* bo = (const float*)d_in[off + 10];
    const float* gammas = (const float*)d_in[off + 11];
    const float* ln1w = (const float*)d_in[off + 12];
    const float* ln1b = (const float*)d_in[off + 13];
    const float* W1 = (const float*)d_in[off + 14];
    const float* b1 = (const float*)d_in[off + 15];
    const float* W2 = (const float*)d_in[off + 16];
    const float* b2 = (const float*)d_in[off + 17];
    const float* ln2w = (const float*)d_in[off + 18];
    const float* ln2b = (const float*)d_in[off + 19];

    float *pattnout, *px, *pf;
    cudaGetSymbolAddress((void**)&pattnout, g_attnout);
    cudaGetSymbolAddress((void**)&px, g_x);
    cudaGetSymbolAddress((void**)&pf, g_f);

    __half *aq,*ak,*av;
    __half *wqh,*wkh,*wvh,*woh,*w1h,*w2h;
    __half *chi,*xh,*hh,*qhi,*qlo,*khi,*vhi;
    cudaGetSymbolAddress((void**)&aq, g_aq);
    cudaGetSymbolAddress((void**)&ak, g_ak);
    cudaGetSymbolAddress((void**)&av, g_av);
    cudaGetSymbolAddress((void**)&wqh, g_wq_h);
    cudaGetSymbolAddress((void**)&wkh, g_wk_h);
    cudaGetSymbolAddress((void**)&wvh, g_wv_h);
    cudaGetSymbolAddress((void**)&woh, g_wo_h);
    cudaGetSymbolAddress((void**)&w1h, g_w1_h);
    cudaGetSymbolAddress((void**)&w2h, g_w2_h);
    cudaGetSymbolAddress((void**)&chi, g_chi);
    cudaGetSymbolAddress((void**)&xh, g_xh);
    cudaGetSymbolAddress((void**)&hh, g_hh);
    cudaGetSymbolAddress((void**)&qhi, g_qhi);   cudaGetSymbolAddress((void**)&qlo, g_qlo);
    cudaGetSymbolAddress((void**)&khi, g_khi);
    cudaGetSymbolAddress((void**)&vhi, g_vhi);

    const int M = BB * SS;   // 4096
    cudaFuncSetAttribute(gemm_mma<false,false>, cudaFuncAttributeMaxDynamicSharedMemorySize, G_SMEM);
    cudaFuncSetAttribute(gemm_mma<false,true>,  cudaFuncAttributeMaxDynamicSharedMemorySize, G_SMEM);
    cudaFuncSetAttribute(gemm_mma<true,true>,   cudaFuncAttributeMaxDynamicSharedMemorySize, G_SMEM);
    cudaFuncSetAttribute(attn_kernel, cudaFuncAttributeMaxDynamicSharedMemorySize, AT_SMEM);

    // -------- #0: split A (QKV activations + QKV weights) --------
    {
        SplitArgs sa;
        const float* srcs[6] = {query, key, values, Wq, Wk, Wv};
        __half* his[6] = {aq, ak, av, wqh, wkh, wvh};
        int nblk[6] = {4096, 4096, 4096, 1024, 1024, 1024};
        int cum = 0;
        for (int i = 0; i < 6; i++) {
            sa.seg[i].src = srcs[i]; sa.seg[i].hi = his[i];
            sa.start[i] = cum; cum += nblk[i];
        }
        for (int i = 6; i < 9; i++) { sa.seg[i] = sa.seg[5]; sa.start[i] = cum; }
        sa.start[9] = cum;
        multi_split_kernel<<<cum, 256>>>(sa);
    }

    // -------- #1: QKV projections --------
    {
        GemmIO q = {aq, wqh, bq, nullptr, qhi, qlo};
        GemmIO k = {ak, wkh, bk, nullptr, khi, nullptr};
        GemmIO v = {av, wvh, bv, nullptr, vhi, nullptr};
        gemm_mma<false,true><<<dim3(DD/128, M/256, 3), 512, G_SMEM>>>(q, k, v, M, DD, DD);
    }

    // -------- #2: split B (Wo, W1, W2 — independent of QKV) --------
    {
        SplitArgs sa;
        const float* srcs[3] = {Wo, W1, W2};
        __half* his[3] = {woh, w1h, w2h};
        int nblk[3] = {1024, 4096, 4096};
        int cum = 0;
        for (int i = 0; i < 3; i++) {
            sa.seg[i].src = srcs[i]; sa.seg[i].hi = his[i];
            sa.start[i] = cum; cum += nblk[i];
        }
        for (int i = 3; i < 9; i++) { sa.seg[i] = sa.seg[2]; sa.start[i] = cum; }
        sa.start[9] = cum;
        multi_split_kernel<<<cum, 256>>>(sa);
    }

    // -------- #3: attention (profiled slot) --------
    attn_kernel<<<dim3(HH*BB, SS/16, 1), 256, AT_SMEM>>>(qhi, qlo, khi, vhi, gammas, chi);

    // -------- #4: output projection --------
    {
        GemmIO o = {chi, woh, bo, pattnout, nullptr, nullptr};
        gemm_mma<false,false><<<dim3(DD/128, M/256, 1), 512, G_SMEM>>>(o, o, o, M, DD, DD);
    }

    // -------- #5: LN1 --------
    add_ln_kernel<true><<<M, 256>>>(query, pattnout, ln1w, ln1b, px, xh);

    // -------- #6: FFN1 (+ReLU) --------
    {
        GemmIO f1 = {xh, w1h, b1, nullptr, hh, nullptr};
        gemm_mma<true,true><<<dim3(DFFF/128, M/256, 1), 512, G_SMEM>>>(f1, f1, f1, M, DFFF, DD);
    }

    // -------- #7: FFN2 --------
    {
        GemmIO f2 = {hh, w2h, b2, pf, nullptr, nullptr};
        gemm_mma<false,false><<<dim3(DD/128, M/256, 1), 512, G_SMEM>>>(f2, f2, f2, M, DD, DFFF);
    }

    // -------- #8: LN2 --------
    add_ln_kernel<false><<<M, 256>>>(px, pf, ln2w, ln2b, (float*)d_out, nullptr);
}

// round 15
// speedup vs baseline: 1.0570x; 1.0570x over previous
#include <cuda_runtime.h>
#include <cuda_fp16.h>
#include <math.h>
#include <stdint.h>

// Problem constants
#define BB 4
#define SS 1024
#define DD 1024
#define HH 16
#define DKK 64
#define DFFF 4096
#define SCP 1032   // score row pitch (floats)

// ---------------- scratch (device globals) -----------------------------------
__device__ float g_attnout[BB*SS*DD];
__device__ float g_x[BB*SS*DD];
__device__ float g_f[BB*SS*DD];
__device__ __half g_aq[BB*SS*DD];
__device__ __half g_ak[BB*SS*DD];
__device__ __half g_av[BB*SS*DD];
__device__ __half g_wq_h[DD*DD];
__device__ __half g_wk_h[DD*DD];
__device__ __half g_wv_h[DD*DD];
__device__ __half g_wo_h[DD*DD];
__device__ __half g_w1_h[DFFF*DD];
__device__ __half g_w2_h[DD*DFFF];
__device__ __half g_chi[BB*SS*DD];
__device__ __half g_xh[BB*SS*DD];
__device__ __half g_hh[BB*SS*DFFF];
__device__ __half g_qhi[BB*SS*DD], g_qlo[BB*SS*DD];
__device__ __half g_khi[BB*SS*DD];
__device__ __half g_vhi[BB*SS*DD];

// ======================= PTX helpers ========================================
__device__ __forceinline__ uint32_t smem_u32(const void* p) {
    uint32_t a;
    asm("{ .reg .u64 t; cvta.to.shared.u64 t, %1; cvt.u32.u64 %0, t; }" : "=r"(a) : "l"(p));
    return a;
}

#define CPASYNC16(dst, src) asm volatile("cp.async.cg.shared.global [%0], [%1], 16;" :: "r"(dst), "l"(src) : "memory")
#define CPCOMMIT() asm volatile("cp.async.commit_group;" ::: "memory")
#define CPWAIT1()  asm volatile("cp.async.wait_group 1;" ::: "memory")
#define CPWAIT0()  asm volatile("cp.async.wait_group 0;" ::: "memory")

#define LDSM_X4(R, A) \
    asm volatile("ldmatrix.sync.aligned.m8n8.x4.shared.b16 {%0,%1,%2,%3}, [%4];" \
        : "=r"((R)[0]), "=r"((R)[1]), "=r"((R)[2]), "=r"((R)[3]) : "r"(A))

#define LDSM_X2T(R, A) \
    asm volatile("ldmatrix.sync.aligned.m8n8.x2.trans.shared.b16 {%0,%1}, [%2];" \
        : "=r"((R)[0]), "=r"((R)[1]) : "r"(A))

__device__ __forceinline__ void mma_f16(float* c, const uint32_t* a, const uint32_t* b) {
    asm volatile(
        "mma.sync.aligned.m16n8k16.row.col.f32.f16.f16.f32 "
        "{%0,%1,%2,%3}, {%4,%5,%6,%7}, {%8,%9}, {%0,%1,%2,%3};"
        : "+f"(c[0]), "+f"(c[1]), "+f"(c[2]), "+f"(c[3])
        : "r"(a[0]), "r"(a[1]), "r"(a[2]), "r"(a[3]), "r"(b[0]), "r"(b[1]));
}

__device__ __forceinline__ uint32_t packh2(float x, float y) {
    __half2 t = __floats2half2_rn(x, y);
    return *reinterpret_cast<uint32_t*>(&t);
}
__device__ __forceinline__ uint32_t packloh2(float x, float y, uint32_t hi) {
    __half2 h = *reinterpret_cast<__half2*>(&hi);
    return packh2(x - __half2float(h.x), y - __half2float(h.y));
}

// ================ mega split: fp32 -> single fp16 ===========================
struct SplitSeg { const float* src; __half* hi; };
struct SplitArgs { SplitSeg seg[9]; int start[10]; };

__global__ void __launch_bounds__(256) multi_split_kernel(SplitArgs a)
{
    int bx = blockIdx.x;
    int s = 0;
#pragma unroll
    for (int i = 0; i < 8; i++) if (bx >= a.start[i+1]) s = i+1;
    SplitSeg sg = a.seg[s];
    int i = (bx - a.start[s]) * 256 + threadIdx.x;
    float4 v = ((const float4*)sg.src)[i];
    uint32_t h0 = packh2(v.x, v.y), h1 = packh2(v.z, v.w);
    ((uint32_t*)sg.hi)[i*2+0] = h0;
    ((uint32_t*)sg.hi)[i*2+1] = h1;
}

// ====== fp16 GEMM: C = A @ W^T + bias, tile 256x128, K-chunk 64, 3 stages ===
#define G_BH 36864
#define G_STAGE 55296
#define G_SMEM (3 * G_STAGE)   // 165888

struct GemmIO {
    const __half *Ah, *Wh;
    const float* bias;
    float* C;
    __half *Chi, *Clo;
};

template<bool RELU, bool SPLITOUT>
__global__ void __launch_bounds__(512, 1) gemm_mma(
    GemmIO io0, GemmIO io1, GemmIO io2, int M, int N, int K)
{
    extern __shared__ __align__(128) char smem[];
    uint32_t sb = smem_u32(smem);

    GemmIO io = (blockIdx.z == 0) ? io0 : (blockIdx.z == 1) ? io1 : io2;

    int tid  = threadIdx.x;
    int lane = tid & 31;
    int wid  = tid >> 5;
    int wm   = wid & 3;
    int wn   = wid >> 2;
    int bm = blockIdx.y * 256;
    int bn = blockIdx.x * 128;

    const int nch = K >> 6;

    auto load_stage = [&](int c) {
        uint32_t st = sb + (c % 3) * G_STAGE;
        size_t kof = (size_t)c * 64;
        const __half* a_h = io.Ah + (size_t)bm * K + kof;
        const __half* b_h = io.Wh + (size_t)bn * K + kof;
#pragma unroll
        for (int u = 0; u < 4; u++) {
            int l = tid + u * 512;
            int row = l >> 3, ch = l & 7;
            CPASYNC16(st + row*144 + ch*16, (const char*)(a_h + (size_t)row*K) + ch*16);
        }
#pragma unroll
        for (int u = 0; u < 2; u++) {
            int l = tid + u * 512;
            int row = l >> 3, ch = l & 7;
            CPASYNC16(st + G_BH + row*144 + ch*16, (const char*)(b_h + (size_t)row*K) + ch*16);
        }
        CPCOMMIT();
    };

    uint32_t aoff = ((((lane >> 3) & 1) * 8 + (lane & 7)) * 144) + (lane >> 4) * 16;
    uint32_t boff = (((lane >> 4) * 8 + (lane & 7)) * 144) + ((lane >> 3) & 1) * 16;

    float acc[4][4][4];
#pragma unroll
    for (int mt = 0; mt < 4; mt++)
#pragma unroll
        for (int n8 = 0; n8 < 4; n8++)
#pragma unroll
            for (int k = 0; k < 4; k++) acc[mt][n8][k] = 0.f;

    load_stage(0);
    load_stage(1);
    for (int c = 0; c < nch; c++) {
        if (c + 1 < nch) { CPWAIT1(); } else { CPWAIT0(); }
        __syncthreads();
        if (c + 2 < nch) load_stage(c + 2);

        uint32_t st = sb + (c % 3) * G_STAGE;
        uint32_t aH = st        + (wm * 64) * 144 + aoff;
        uint32_t bH = st + G_BH + (wn * 32) * 144 + boff;

#pragma unroll
        for (int ks = 0; ks < 4; ks++) {
            uint32_t ah[4][4];
#pragma unroll
            for (int mt = 0; mt < 4; mt++)
                LDSM_X4(ah[mt], aH + mt * (16*144) + ks * 32);
#pragma unroll
            for (int g = 0; g < 2; g++) {
                uint32_t bh[4];
                LDSM_X4(bh, bH + g * (16*144) + ks * 32);
#pragma unroll
                for (int mt = 0; mt < 4; mt++)
#pragma unroll
                    for (int hf = 0; hf < 2; hf++)
                        mma_f16(acc[mt][g*2+hf], ah[mt], &bh[hf*2]);
            }
        }
    }

    int r_in = lane >> 2;
    int c_in = (lane & 3) * 2;
    bool wlo = SPLITOUT && (io.Clo != nullptr);
#pragma unroll
    for (int mt = 0; mt < 4; mt++) {
        int R0 = bm + wm * 64 + mt * 16 + r_in;
        int R1 = R0 + 8;
#pragma unroll
        for (int n8 = 0; n8 < 4; n8++) {
            int col = bn + wn * 32 + n8 * 8 + c_in;
            float b0 = io.bias[col], b1 = io.bias[col + 1];
            float o00 = acc[mt][n8][0] + b0, o01 = acc[mt][n8][1] + b1;
            float o10 = acc[mt][n8][2] + b0, o11 = acc[mt][n8][3] + b1;
            if (RELU) {
                o00 = fmaxf(o00, 0.f); o01 = fmaxf(o01, 0.f);
                o10 = fmaxf(o10, 0.f); o11 = fmaxf(o11, 0.f);
            }
            if (SPLITOUT) {
                uint32_t h0 = packh2(o00, o01), h1 = packh2(o10, o11);
                *(uint32_t*)&io.Chi[(size_t)R0 * N + col] = h0;
                *(uint32_t*)&io.Chi[(size_t)R1 * N + col] = h1;
                if (wlo) {
                    uint32_t l0 = packloh2(o00, o01, h0), l1 = packloh2(o10, o11, h1);
                    *(uint32_t*)&io.Clo[(size_t)R0 * N + col] = l0;
                    *(uint32_t*)&io.Clo[(size_t)R1 * N + col] = l1;
                }
            } else {
                float2 o0, o1;
                o0.x = o00; o0.y = o01; o1.x = o10; o1.y = o11;
                *(float2*)&io.C[(size_t)R0 * N + col] = o0;
                *(float2*)&io.C[(size_t)R1 * N + col] = o1;
            }
        }
    }
}

// ================= tensor-core distance-decay attention ======================
// 512 threads, 32 rows/CTA, K/V tiles 256 rows. Grid (64, 32) wave-balanced.
// Row math: lean 3-pass (no max subtraction — scores are O(1); fused sum2).
#define AT_QH 132096
#define AT_QL 136704
#define AT_K  141312
#define AT_KSZ 36864
#define AT_SMEM 215040

__global__ void __launch_bounds__(512, 1) attn_kernel(
    const __half* __restrict__ qhi, const __half* __restrict__ qlo,
    const __half* __restrict__ khi, const __half* __restrict__ vhi,
    const float* __restrict__ gammas,
    __half* __restrict__ ohi)
{
    extern __shared__ __align__(128) char smx[];
    float* sc = (float*)smx;
    uint32_t sb = smem_u32(smx);
    const uint32_t QH = sb + AT_QH;
    const uint32_t QL = sb + AT_QL;

    int h = blockIdx.x & 15, b = blockIdx.x >> 4;
    int i0 = blockIdx.y * 32;
    int t = threadIdx.x, lane = t & 31, w = t >> 5;
    int mt = w & 1;
    int cg = w >> 1;

    size_t base_q = ((size_t)b*SS + i0)*DD + h*64;
    size_t base_k = (size_t)b*SS*DD + h*64;

    // ---- load Q tile (32 rows, hi+lo)
    {
        int sel = t >> 8;
        int idx = t & 255;
        int row = idx >> 3, ch = idx & 7;
        const __half* src = (sel ? qlo : qhi) + base_q + (size_t)row*DD + ch*8;
        char* dst = smx + (sel ? AT_QL : AT_QH) + row*144 + ch*16;
        *(float4*)dst = *(const float4*)src;
    }
    __syncthreads();

    uint32_t aoff = ((((lane >> 3) & 1) * 8 + (lane & 7)) * 144) + (lane >> 4) * 16;
    uint32_t boff = (((lane >> 4) * 8 + (lane & 7)) * 144) + ((lane >> 3) & 1) * 16;

    uint32_t ah[4][4], al[4][4];
#pragma unroll
    for (int ks = 0; ks < 4; ks++) {
        LDSM_X4(ah[ks], QH + mt*(16*144) + aoff + ks*32);
        LDSM_X4(al[ks], QL + mt*(16*144) + aoff + ks*32);
    }

    auto loadK = [&](int jt, int bf) {
        uint32_t KH = sb + AT_K + bf * AT_KSZ;
        int jbase = jt * 256;
#pragma unroll
        for (int u = 0; u < 4; u++) {
            int l = t + u * 512;
            int row = l >> 3, ch = l & 7;
            const char* sh = (const char*)(khi + base_k + (size_t)(jbase+row)*DD) + ch*16;
            CPASYNC16(KH + row*144 + ch*16, sh);
        }
        CPCOMMIT();
    };

    // ---- QK^T: 4 tiles of 256 cols, double-buffered
    loadK(0, 0);
    for (int jt = 0; jt < 4; jt++) {
        CPWAIT0();
        __syncthreads();
        if (jt + 1 < 4) loadK(jt + 1, (jt + 1) & 1);

        uint32_t KH = sb + AT_K + (jt & 1) * AT_KSZ;
#pragma unroll
        for (int half = 0; half < 2; half++) {
            float c0[4] = {0,0,0,0}, c1[4] = {0,0,0,0};
            uint32_t bb = (uint32_t)(half*128 + cg*16)*144 + boff;
#pragma unroll
            for (int ks = 0; ks < 4; ks++) {
                uint32_t bh[4];
                LDSM_X4(bh, KH + bb + ks*32);
                mma_f16(c0, ah[ks], &bh[0]);
                mma_f16(c0, al[ks], &bh[0]);
                mma_f16(c1, ah[ks], &bh[2]);
                mma_f16(c1, al[ks], &bh[2]);
            }
            int r0 = mt*16 + (lane >> 2);
            int cb = jt*256 + half*128 + cg*16 + (lane & 3)*2;
            float2 v2;
            v2.x = c0[0]*0.125f; v2.y = c0[1]*0.125f; *(float2*)&sc[r0*SCP + cb] = v2;
            v2.x = c0[2]*0.125f; v2.y = c0[3]*0.125f; *(float2*)&sc[(r0+8)*SCP + cb] = v2;
            v2.x = c1[0]*0.125f; v2.y = c1[1]*0.125f; *(float2*)&sc[r0*SCP + cb + 8] = v2;
            v2.x = c1[2]*0.125f; v2.y = c1[3]*0.125f; *(float2*)&sc[(r0+8)*SCP + cb + 8] = v2;
        }
    }

    int jmax = i0 + 32;
    auto loadV = [&](int jbase, int rows, int bf) {
        uint32_t VH = sb + AT_K + bf * AT_KSZ;
        int total = rows * 8;
#pragma unroll
        for (int u = 0; u < 4; u++) {
            int l = t + u * 512;
            if (l < total) {
                int row = l >> 3, ch = l & 7;
                const char* sh = (const char*)(vhi + base_k + (size_t)(jbase+row)*DD) + ch*16;
                CPASYNC16(VH + row*144 + ch*16, sh);
            }
        }
        CPCOMMIT();
    };

    // prefetch V tile 0 (hidden under row math)
    loadV(0, jmax < 256 ? jmax : 256, 0);
    __syncthreads();

    // ---- per-row math: LEAN 3-pass, no max subtraction
    {
        float gamma = -log1pf(__expf(gammas[h]));
        for (int rr2 = 0; rr2 < 2; rr2++) {
            int r  = w*2 + rr2;
            int ig = i0 + r;
            float* row = sc + r*SCP;
            int cmask = ig >> 5;           // boundary chunk

            // pass B: sums (full/boundary/unmasked split — predicate only at boundary)
            float sum1 = 0.f, summ = 0.f;
            {
                const float* pr = row + lane;
                int c = 0;
                for (; c < cmask; c++) {
                    float p = __expf(pr[c*32]);
                    sum1 += p; summ += p;
                }
                {
                    int j = cmask*32 + lane;
                    float p = __expf(pr[cmask*32]);
                    sum1 += p;
                    if (j <= ig) summ += p;
                }
                for (c = cmask + 1; c < 32; c++)
                    sum1 += __expf(pr[c*32]);
            }
#pragma unroll
            for (int o = 16; o > 0; o >>= 1) {
                sum1 += __shfl_xor_sync(0xffffffffu, sum1, o);
                summ += __shfl_xor_sync(0xffffffffu, summ, o);
            }
            float inv1 = 1.f / sum1;

            // pass C: scan + decay + exp + sum2, 2 chunks/iter
            float carry = 0.f, sum2 = 0.f;
            for (int c = 0; c <= cmask; c += 2) {
                int j0 = c*32 + lane;
                int j1 = j0 + 32;
                bool has1 = (c + 1 <= cmask);
                float s0 = row[j0];
                float s1v = has1 ? row[j1] : 0.f;
                float x0 = (j0 <= ig) ? __expf(s0) : 0.f;
                float x1 = (has1 && j1 <= ig) ? __expf(s1v) : 0.f;
#pragma unroll
                for (int o = 1; o < 32; o <<= 1) {
                    float y0 = __shfl_up_sync(0xffffffffu, x0, o);
                    float y1 = __shfl_up_sync(0xffffffffu, x1, o);
                    if (lane >= o) { x0 += y0; x1 += y1; }
                }
                float t0 = __shfl_sync(0xffffffffu, x0, 31);
                float t1 = __shfl_sync(0xffffffffu, x1, 31);
                float d0 = carry + x0;
                float d1 = carry + t0 + x1;
                carry += t0 + t1;
                {
                    float pos  = fabsf((float)(ig - j0));
                    float dd   = (summ - d0) * inv1 * pos;
                    float dist = sqrtf(fmaxf(dd, 0.f));
                    float eff  = fminf(fmaxf(__expf(dist * gamma), 1e-5f), 1e5f);
                    float e2 = (j0 <= ig) ? __expf(s0 * eff) : 0.f;
                    row[j0] = e2;
                    sum2 += e2;
                }
                if (has1) {
                    float pos  = fabsf((float)(ig - j1));
                    float dd   = (summ - d1) * inv1 * pos;
                    float dist = sqrtf(fmaxf(dd, 0.f));
                    float eff  = fminf(fmaxf(__expf(dist * gamma), 1e-5f), 1e5f);
                    float e2 = (j1 <= ig) ? __expf(s1v * eff) : 0.f;
                    row[j1] = e2;
                    sum2 += e2;
                }
            }
#pragma unroll
            for (int o = 16; o > 0; o >>= 1) sum2 += __shfl_xor_sync(0xffffffffu, sum2, o);
            float inv2 = 1.f / sum2;

            // pass E: normalize masked chunks; zero tail up to jmax
            int clim = (jmax + 31) >> 5;
            for (int c = 0; c <= cmask; c++) row[c*32 + lane] *= inv2;
            for (int c = cmask + 1; c < clim; c++) row[c*32 + lane] = 0.f;
        }
    }

    // ---- PV
    float acc[4] = {0.f, 0.f, 0.f, 0.f};
    int rr = lane >> 2, kc = (lane & 3) * 2;
    int vrow = lane & 15;
    int ntiles = (jmax + 255) >> 8;
    for (int ji = 0; ji < ntiles; ji++) {
        int jbase = ji * 256;
        int rows = jmax - jbase; if (rows > 256) rows = 256;
        CPWAIT0();
        __syncthreads();
        if (ji + 1 < ntiles) {
            int nb = jbase + 256;
            int nrows = jmax - nb; if (nrows > 256) nrows = 256;
            loadV(nb, nrows, (ji + 1) & 1);
        }
        uint32_t VH = sb + AT_K + (ji & 1) * AT_KSZ;

        int nk = rows >> 4;
        for (int kk = 0; kk < nk; kk++) {
            int j0 = jbase + kk*16;
            uint32_t vh[2];
            uint32_t va = (uint32_t)(kk*16 + vrow)*144 + (uint32_t)cg*16;
            LDSM_X2T(vh, VH + va);
            const float* p0 = &sc[(mt*16 + rr)*SCP + j0 + kc];
            float f00 = p0[0],        f01 = p0[1];
            float f10 = p0[8*SCP],    f11 = p0[8*SCP+1];
            float f20 = p0[8],        f21 = p0[9];
            float f30 = p0[8*SCP+8],  f31 = p0[8*SCP+9];
            uint32_t a_h[4], a_l[4];
            a_h[0] = packh2(f00, f01); a_l[0] = packloh2(f00, f01, a_h[0]);
            a_h[1] = packh2(f10, f11); a_l[1] = packloh2(f10, f11, a_h[1]);
            a_h[2] = packh2(f20, f21); a_l[2] = packloh2(f20, f21, a_h[2]);
            a_h[3] = packh2(f30, f31); a_l[3] = packloh2(f30, f31, a_h[3]);
            mma_f16(acc, a_h, vh);
            mma_f16(acc, a_l, vh);
        }
    }

    // ---- epilogue -> concat single fp16
    {
        size_t o0 = ((size_t)b*SS + i0 + mt*16 + rr)*DD + h*64 + cg*8 + kc;
        size_t o1 = o0 + (size_t)8*DD;
        *(uint32_t*)&ohi[o0] = packh2(acc[0], acc[1]);
        *(uint32_t*)&ohi[o1] = packh2(acc[2], acc[3]);
    }
}

// ---------------- residual add + LayerNorm ----------------------------------
template<bool SPLITOUT>
__global__ void __launch_bounds__(256) add_ln_kernel(
    const float* __restrict__ A, const float* __restrict__ Bres,
    const float* __restrict__ w, const float* __restrict__ bias,
    float* __restrict__ outp,
    __half* __restrict__ ohi)
{
    __shared__ float red1[8], red2[8];
    int row = blockIdx.x;
    int t   = threadIdx.x;
    const float* pa = A    + (size_t)row*DD;
    const float* pb = Bres + (size_t)row*DD;

    float4 a4 = *(const float4*)&pa[t*4];
    float4 b4 = *(const float4*)&pb[t*4];
    float v0 = a4.x + b4.x, v1 = a4.y + b4.y, v2 = a4.z + b4.z, v3 = a4.w + b4.w;

    int lane = t & 31, wp = t >> 5;
    float s = v0 + v1 + v2 + v3;
#pragma unroll
    for (int o = 16; o > 0; o >>= 1) s += __shfl_xor_sync(0xffffffffu, s, o);
    if (lane == 0) red1[wp] = s;
    __syncthreads();
    float tot = 0.f;
#pragma unroll
    for (int i = 0; i < 8; i++) tot += red1[i];
    float mu = tot * (1.f / DD);

    float d0 = v0-mu, d1 = v1-mu, d2 = v2-mu, d3 = v3-mu;
    float q2 = d0*d0 + d1*d1 + d2*d2 + d3*d3;
#pragma unroll
    for (int o = 16; o > 0; o >>= 1) q2 += __shfl_xor_sync(0xffffffffu, q2, o);
    if (lane == 0) red2[wp] = q2;
    __syncthreads();
    float tv = 0.f;
#pragma unroll
    for (int i = 0; i < 8; i++) tv += red2[i];
    float inv = rsqrtf(tv * (1.f / DD) + 1e-5f);

    float4 w4  = *(const float4*)&w[t*4];
    float4 bi4 = *(const float4*)&bias[t*4];
    float4 o4;
    o4.x = d0*inv*w4.x + bi4.x;
    o4.y = d1*inv*w4.y + bi4.y;
    o4.z = d2*inv*w4.z + bi4.z;
    o4.w = d3*inv*w4.w + bi4.w;
    *(float4*)&outp[(size_t)row*DD + t*4] = o4;

    if (SPLITOUT) {
        uint32_t h0 = packh2(o4.x, o4.y), h1 = packh2(o4.z, o4.w);
        size_t base2 = (size_t)row * (DD/2) + t*2;
        ((uint32_t*)ohi)[base2]     = h0;
        ((uint32_t*)ohi)[base2 + 1] = h1;
    }
}

// ---------------- launcher ---------------------------------------------------
extern "C" void kernel_launch(void* const* d_in, const int* in_sizes, int n_in,
                              void* d_out, int out_size)
{
    int off = (in_sizes[0] == 1) ? 1 : 0;
    const float* query  = (const float*)d_in[off + 0];
    const float* key    = (const float*)d_in[off + 1];
    const float* values = (const float*)d_in[off + 2];
    const float* Wq = (const float*)d_in[off + 3];
    const float* bq = (const float*)d_in[off + 4];
    const float* Wk = (const float*)d_in[off + 5];
    const float* bk = (const float*)d_in[off + 6];
    const float* Wv = (const float*)d_in[off + 7];
    const float* bv = (const float*)d_in[off + 8];
    const float* Wo = (const float*)d_in[off + 9];
    const float* bo = (const float*)d_in[off + 10];
    const float* gammas = (const float*)d_in[off + 11];
    const float* ln1w = (const float*)d_in[off + 12];
    const float* ln1b = (const float*)d_in[off + 13];
    const float* W1 = (const float*)d_in[off + 14];
    const float* b1 = (const float*)d_in[off + 15];
    const float* W2 = (const float*)d_in[off + 16];
    const float* b2 = (const float*)d_in[off + 17];
    const float* ln2w = (const float*)d_in[off + 18];
    const float* ln2b = (const float*)d_in[off + 19];

    float *pattnout, *px, *pf;
    cudaGetSymbolAddress((void**)&pattnout, g_attnout);
    cudaGetSymbolAddress((void**)&px, g_x);
    cudaGetSymbolAddress((void**)&pf, g_f);

    __half *aq,*ak,*av;
    __half *wqh,*wkh,*wvh,*woh,*w1h,*w2h;
    __half *chi,*xh,*hh,*qhi,*qlo,*khi,*vhi;
    cudaGetSymbolAddress((void**)&aq, g_aq);
    cudaGetSymbolAddress((void**)&ak, g_ak);
    cudaGetSymbolAddress((void**)&av, g_av);
    cudaGetSymbolAddress((void**)&wqh, g_wq_h);
    cudaGetSymbolAddress((void**)&wkh, g_wk_h);
    cudaGetSymbolAddress((void**)&wvh, g_wv_h);
    cudaGetSymbolAddress((void**)&woh, g_wo_h);
    cudaGetSymbolAddress((void**)&w1h, g_w1_h);
    cudaGetSymbolAddress((void**)&w2h, g_w2_h);
    cudaGetSymbolAddress((void**)&chi, g_chi);
    cudaGetSymbolAddress((void**)&xh, g_xh);
    cudaGetSymbolAddress((void**)&hh, g_hh);
    cudaGetSymbolAddress((void**)&qhi, g_qhi);   cudaGetSymbolAddress((void**)&qlo, g_qlo);
    cudaGetSymbolAddress((void**)&khi, g_khi);
    cudaGetSymbolAddress((void**)&vhi, g_vhi);

    const int M = BB * SS;   // 4096
    cudaFuncSetAttribute(gemm_mma<false,false>, cudaFuncAttributeMaxDynamicSharedMemorySize, G_SMEM);
    cudaFuncSetAttribute(gemm_mma<false,true>,  cudaFuncAttributeMaxDynamicSharedMemorySize, G_SMEM);
    cudaFuncSetAttribute(gemm_mma<true,true>,   cudaFuncAttributeMaxDynamicSharedMemorySize, G_SMEM);
    cudaFuncSetAttribute(attn_kernel, cudaFuncAttributeMaxDynamicSharedMemorySize, AT_SMEM);

    // -------- #0: split A (QKV activations + QKV weights) --------
    {
        SplitArgs sa;
        const float* srcs[6] = {query, key, values, Wq, Wk, Wv};
        __half* his[6] = {aq, ak, av, wqh, wkh, wvh};
        int nblk[6] = {4096, 4096, 4096, 1024, 1024, 1024};
        int cum = 0;
        for (int i = 0; i < 6; i++) {
            sa.seg[i].src = srcs[i]; sa.seg[i].hi = his[i];
            sa.start[i] = cum; cum += nblk[i];
        }
        for (int i = 6; i < 9; i++) { sa.seg[i] = sa.seg[5]; sa.start[i] = cum; }
        sa.start[9] = cum;
        multi_split_kernel<<<cum, 256>>>(sa);
    }

    // -------- #1: QKV projections --------
    {
        GemmIO q = {aq, wqh, bq, nullptr, qhi, qlo};
        GemmIO k = {ak, wkh, bk, nullptr, khi, nullptr};
        GemmIO v = {av, wvh, bv, nullptr, vhi, nullptr};
        gemm_mma<false,true><<<dim3(DD/128, M/256, 3), 512, G_SMEM>>>(q, k, v, M, DD, DD);
    }

    // -------- #2: split B (Wo, W1, W2) --------
    {
        SplitArgs sa;
        const float* srcs[3] = {Wo, W1, W2};
        __half* his[3] = {woh, w1h, w2h};
        int nblk[3] = {1024, 4096, 4096};
        int cum = 0;
        for (int i = 0; i < 3; i++) {
            sa.seg[i].src = srcs[i]; sa.seg[i].hi = his[i];
            sa.start[i] = cum; cum += nblk[i];
        }
        for (int i = 3; i < 9; i++) { sa.seg[i] = sa.seg[2]; sa.start[i] = cum; }
        sa.start[9] = cum;
        multi_split_kernel<<<cum, 256>>>(sa);
    }

    // -------- #3: attention (profiled slot) --------
    attn_kernel<<<dim3(HH*BB, SS/32, 1), 512, AT_SMEM>>>(qhi, qlo, khi, vhi, gammas, chi);

    // -------- #4: output projection --------
    {
        GemmIO o = {chi, woh, bo, pattnout, nullptr, nullptr};
        gemm_mma<false,false><<<dim3(DD/128, M/256, 1), 512, G_SMEM>>>(o, o, o, M, DD, DD);
    }

    // -------- #5: LN1 --------
    add_ln_kernel<true><<<M, 256>>>(query, pattnout, ln1w, ln1b, px, xh);

    // -------- #6: FFN1 (+ReLU) --------
    {
        GemmIO f1 = {xh, w1h, b1, nullptr, hh, nullptr};
        gemm_mma<true,true><<<dim3(DFFF/128, M/256, 1), 512, G_SMEM>>>(f1, f1, f1, M, DFFF, DD);
    }

    // -------- #7: FFN2 --------
    {
        GemmIO f2 = {hh, w2h, b2, pf, nullptr, nullptr};
        gemm_mma<false,false><<<dim3(DD/128, M/256, 1), 512, G_SMEM>>>(f2, f2, f2, M, DD, DFFF);
    }

    // -------- #8: LN2 --------
    add_ln_kernel<false><<<M, 256>>>(px, pf, ln2w, ln2b, (float*)d_out, nullptr);
}

// round 16
// speedup vs baseline: 1.0725x; 1.0146x over previous
#include <cuda_runtime.h>
#include <cuda_fp16.h>
#include <math.h>
#include <stdint.h>

// Problem constants
#define BB 4
#define SS 1024
#define DD 1024
#define HH 16
#define DKK 64
#define DFFF 4096
#define SCP 1032   // score row pitch (floats); slot [1024] holds per-row inv2

// ---------------- scratch (device globals) -----------------------------------
__device__ float g_attnout[BB*SS*DD];
__device__ float g_x[BB*SS*DD];
__device__ float g_f[BB*SS*DD];
__device__ __half g_aq[BB*SS*DD];
__device__ __half g_ak[BB*SS*DD];
__device__ __half g_av[BB*SS*DD];
__device__ __half g_wq_h[DD*DD];
__device__ __half g_wk_h[DD*DD];
__device__ __half g_wv_h[DD*DD];
__device__ __half g_wo_h[DD*DD];
__device__ __half g_w1_h[DFFF*DD];
__device__ __half g_w2_h[DD*DFFF];
__device__ __half g_chi[BB*SS*DD];
__device__ __half g_xh[BB*SS*DD];
__device__ __half g_hh[BB*SS*DFFF];
__device__ __half g_qhi[BB*SS*DD], g_qlo[BB*SS*DD];
__device__ __half g_khi[BB*SS*DD];
__device__ __half g_vhi[BB*SS*DD];

// ======================= PTX helpers ========================================
__device__ __forceinline__ uint32_t smem_u32(const void* p) {
    uint32_t a;
    asm("{ .reg .u64 t; cvta.to.shared.u64 t, %1; cvt.u32.u64 %0, t; }" : "=r"(a) : "l"(p));
    return a;
}

#define CPASYNC16(dst, src) asm volatile("cp.async.cg.shared.global [%0], [%1], 16;" :: "r"(dst), "l"(src) : "memory")
#define CPCOMMIT() asm volatile("cp.async.commit_group;" ::: "memory")
#define CPWAIT1()  asm volatile("cp.async.wait_group 1;" ::: "memory")
#define CPWAIT0()  asm volatile("cp.async.wait_group 0;" ::: "memory")

#define LDSM_X4(R, A) \
    asm volatile("ldmatrix.sync.aligned.m8n8.x4.shared.b16 {%0,%1,%2,%3}, [%4];" \
        : "=r"((R)[0]), "=r"((R)[1]), "=r"((R)[2]), "=r"((R)[3]) : "r"(A))

#define LDSM_X2T(R, A) \
    asm volatile("ldmatrix.sync.aligned.m8n8.x2.trans.shared.b16 {%0,%1}, [%2];" \
        : "=r"((R)[0]), "=r"((R)[1]) : "r"(A))

__device__ __forceinline__ void mma_f16(float* c, const uint32_t* a, const uint32_t* b) {
    asm volatile(
        "mma.sync.aligned.m16n8k16.row.col.f32.f16.f16.f32 "
        "{%0,%1,%2,%3}, {%4,%5,%6,%7}, {%8,%9}, {%0,%1,%2,%3};"
        : "+f"(c[0]), "+f"(c[1]), "+f"(c[2]), "+f"(c[3])
        : "r"(a[0]), "r"(a[1]), "r"(a[2]), "r"(a[3]), "r"(b[0]), "r"(b[1]));
}

__device__ __forceinline__ uint32_t packh2(float x, float y) {
    __half2 t = __floats2half2_rn(x, y);
    return *reinterpret_cast<uint32_t*>(&t);
}
__device__ __forceinline__ uint32_t packloh2(float x, float y, uint32_t hi) {
    __half2 h = *reinterpret_cast<__half2*>(&hi);
    return packh2(x - __half2float(h.x), y - __half2float(h.y));
}

// ================ mega split: fp32 -> single fp16 ===========================
struct SplitSeg { const float* src; __half* hi; };
struct SplitArgs { SplitSeg seg[9]; int start[10]; };

__global__ void __launch_bounds__(256) multi_split_kernel(SplitArgs a)
{
    int bx = blockIdx.x;
    int s = 0;
#pragma unroll
    for (int i = 0; i < 8; i++) if (bx >= a.start[i+1]) s = i+1;
    SplitSeg sg = a.seg[s];
    int i = (bx - a.start[s]) * 256 + threadIdx.x;
    float4 v = ((const float4*)sg.src)[i];
    uint32_t h0 = packh2(v.x, v.y), h1 = packh2(v.z, v.w);
    ((uint32_t*)sg.hi)[i*2+0] = h0;
    ((uint32_t*)sg.hi)[i*2+1] = h1;
}

// ====== fp16 GEMM: C = A @ W^T + bias, tile 256x128, K-chunk 64, 3 stages ===
#define G_BH 36864
#define G_STAGE 55296
#define G_SMEM (3 * G_STAGE)   // 165888

struct GemmIO {
    const __half *Ah, *Wh;
    const float* bias;
    float* C;
    __half *Chi, *Clo;
};

template<bool RELU, bool SPLITOUT>
__global__ void __launch_bounds__(512, 1) gemm_mma(
    GemmIO io0, GemmIO io1, GemmIO io2, int M, int N, int K)
{
    extern __shared__ __align__(128) char smem[];
    uint32_t sb = smem_u32(smem);

    GemmIO io = (blockIdx.z == 0) ? io0 : (blockIdx.z == 1) ? io1 : io2;

    int tid  = threadIdx.x;
    int lane = tid & 31;
    int wid  = tid >> 5;
    int wm   = wid & 3;
    int wn   = wid >> 2;
    int bm = blockIdx.y * 256;
    int bn = blockIdx.x * 128;

    const int nch = K >> 6;

    auto load_stage = [&](int c) {
        uint32_t st = sb + (c % 3) * G_STAGE;
        size_t kof = (size_t)c * 64;
        const __half* a_h = io.Ah + (size_t)bm * K + kof;
        const __half* b_h = io.Wh + (size_t)bn * K + kof;
#pragma unroll
        for (int u = 0; u < 4; u++) {
            int l = tid + u * 512;
            int row = l >> 3, ch = l & 7;
            CPASYNC16(st + row*144 + ch*16, (const char*)(a_h + (size_t)row*K) + ch*16);
        }
#pragma unroll
        for (int u = 0; u < 2; u++) {
            int l = tid + u * 512;
            int row = l >> 3, ch = l & 7;
            CPASYNC16(st + G_BH + row*144 + ch*16, (const char*)(b_h + (size_t)row*K) + ch*16);
        }
        CPCOMMIT();
    };

    uint32_t aoff = ((((lane >> 3) & 1) * 8 + (lane & 7)) * 144) + (lane >> 4) * 16;
    uint32_t boff = (((lane >> 4) * 8 + (lane & 7)) * 144) + ((lane >> 3) & 1) * 16;

    float acc[4][4][4];
#pragma unroll
    for (int mt = 0; mt < 4; mt++)
#pragma unroll
        for (int n8 = 0; n8 < 4; n8++)
#pragma unroll
            for (int k = 0; k < 4; k++) acc[mt][n8][k] = 0.f;

    load_stage(0);
    load_stage(1);
    for (int c = 0; c < nch; c++) {
        if (c + 1 < nch) { CPWAIT1(); } else { CPWAIT0(); }
        __syncthreads();
        if (c + 2 < nch) load_stage(c + 2);

        uint32_t st = sb + (c % 3) * G_STAGE;
        uint32_t aH = st        + (wm * 64) * 144 + aoff;
        uint32_t bH = st + G_BH + (wn * 32) * 144 + boff;

#pragma unroll
        for (int ks = 0; ks < 4; ks++) {
            uint32_t ah[4][4];
#pragma unroll
            for (int mt = 0; mt < 4; mt++)
                LDSM_X4(ah[mt], aH + mt * (16*144) + ks * 32);
#pragma unroll
            for (int g = 0; g < 2; g++) {
                uint32_t bh[4];
                LDSM_X4(bh, bH + g * (16*144) + ks * 32);
#pragma unroll
                for (int mt = 0; mt < 4; mt++)
#pragma unroll
                    for (int hf = 0; hf < 2; hf++)
                        mma_f16(acc[mt][g*2+hf], ah[mt], &bh[hf*2]);
            }
        }
    }

    int r_in = lane >> 2;
    int c_in = (lane & 3) * 2;
    bool wlo = SPLITOUT && (io.Clo != nullptr);
#pragma unroll
    for (int mt = 0; mt < 4; mt++) {
        int R0 = bm + wm * 64 + mt * 16 + r_in;
        int R1 = R0 + 8;
#pragma unroll
        for (int n8 = 0; n8 < 4; n8++) {
            int col = bn + wn * 32 + n8 * 8 + c_in;
            float b0 = io.bias[col], b1 = io.bias[col + 1];
            float o00 = acc[mt][n8][0] + b0, o01 = acc[mt][n8][1] + b1;
            float o10 = acc[mt][n8][2] + b0, o11 = acc[mt][n8][3] + b1;
            if (RELU) {
                o00 = fmaxf(o00, 0.f); o01 = fmaxf(o01, 0.f);
                o10 = fmaxf(o10, 0.f); o11 = fmaxf(o11, 0.f);
            }
            if (SPLITOUT) {
                uint32_t h0 = packh2(o00, o01), h1 = packh2(o10, o11);
                *(uint32_t*)&io.Chi[(size_t)R0 * N + col] = h0;
                *(uint32_t*)&io.Chi[(size_t)R1 * N + col] = h1;
                if (wlo) {
                    uint32_t l0 = packloh2(o00, o01, h0), l1 = packloh2(o10, o11, h1);
                    *(uint32_t*)&io.Clo[(size_t)R0 * N + col] = l0;
                    *(uint32_t*)&io.Clo[(size_t)R1 * N + col] = l1;
                }
            } else {
                float2 o0, o1;
                o0.x = o00; o0.y = o01; o1.x = o10; o1.y = o11;
                *(float2*)&io.C[(size_t)R0 * N + col] = o0;
                *(float2*)&io.C[(size_t)R1 * N + col] = o1;
            }
        }
    }
}

// ================= tensor-core distance-decay attention ======================
// 512 threads, 32 rows/CTA, K/V tiles 256 rows. Grid (64, 32) wave-balanced.
// Row math: lean, no max subtraction. Probs stored PACKED half2(hi,lo) in sc;
// normalization folded into PV epilogue (inv2 cached at sc[r][1024]).
#define AT_QH 132096
#define AT_QL 136704
#define AT_K  141312
#define AT_KSZ 36864
#define AT_SMEM 215040

__global__ void __launch_bounds__(512, 1) attn_kernel(
    const __half* __restrict__ qhi, const __half* __restrict__ qlo,
    const __half* __restrict__ khi, const __half* __restrict__ vhi,
    const float* __restrict__ gammas,
    __half* __restrict__ ohi)
{
    extern __shared__ __align__(128) char smx[];
    float* sc = (float*)smx;
    uint32_t sb = smem_u32(smx);
    const uint32_t QH = sb + AT_QH;
    const uint32_t QL = sb + AT_QL;

    int h = blockIdx.x & 15, b = blockIdx.x >> 4;
    int i0 = blockIdx.y * 32;
    int t = threadIdx.x, lane = t & 31, w = t >> 5;
    int mt = w & 1;
    int cg = w >> 1;

    size_t base_q = ((size_t)b*SS + i0)*DD + h*64;
    size_t base_k = (size_t)b*SS*DD + h*64;

    // ---- load Q tile (32 rows, hi+lo)
    {
        int sel = t >> 8;
        int idx = t & 255;
        int row = idx >> 3, ch = idx & 7;
        const __half* src = (sel ? qlo : qhi) + base_q + (size_t)row*DD + ch*8;
        char* dst = smx + (sel ? AT_QL : AT_QH) + row*144 + ch*16;
        *(float4*)dst = *(const float4*)src;
    }
    __syncthreads();

    uint32_t aoff = ((((lane >> 3) & 1) * 8 + (lane & 7)) * 144) + (lane >> 4) * 16;
    uint32_t boff = (((lane >> 4) * 8 + (lane & 7)) * 144) + ((lane >> 3) & 1) * 16;

    uint32_t ah[4][4], al[4][4];
#pragma unroll
    for (int ks = 0; ks < 4; ks++) {
        LDSM_X4(ah[ks], QH + mt*(16*144) + aoff + ks*32);
        LDSM_X4(al[ks], QL + mt*(16*144) + aoff + ks*32);
    }

    auto loadK = [&](int jt, int bf) {
        uint32_t KH = sb + AT_K + bf * AT_KSZ;
        int jbase = jt * 256;
#pragma unroll
        for (int u = 0; u < 4; u++) {
            int l = t + u * 512;
            int row = l >> 3, ch = l & 7;
            const char* sh = (const char*)(khi + base_k + (size_t)(jbase+row)*DD) + ch*16;
            CPASYNC16(KH + row*144 + ch*16, sh);
        }
        CPCOMMIT();
    };

    // ---- QK^T: 4 tiles of 256 cols, double-buffered
    loadK(0, 0);
    for (int jt = 0; jt < 4; jt++) {
        CPWAIT0();
        __syncthreads();
        if (jt + 1 < 4) loadK(jt + 1, (jt + 1) & 1);

        uint32_t KH = sb + AT_K + (jt & 1) * AT_KSZ;
#pragma unroll
        for (int half = 0; half < 2; half++) {
            float c0[4] = {0,0,0,0}, c1[4] = {0,0,0,0};
            uint32_t bb = (uint32_t)(half*128 + cg*16)*144 + boff;
#pragma unroll
            for (int ks = 0; ks < 4; ks++) {
                uint32_t bh[4];
                LDSM_X4(bh, KH + bb + ks*32);
                mma_f16(c0, ah[ks], &bh[0]);
                mma_f16(c0, al[ks], &bh[0]);
                mma_f16(c1, ah[ks], &bh[2]);
                mma_f16(c1, al[ks], &bh[2]);
            }
            int r0 = mt*16 + (lane >> 2);
            int cb = jt*256 + half*128 + cg*16 + (lane & 3)*2;
            float2 v2;
            v2.x = c0[0]*0.125f; v2.y = c0[1]*0.125f; *(float2*)&sc[r0*SCP + cb] = v2;
            v2.x = c0[2]*0.125f; v2.y = c0[3]*0.125f; *(float2*)&sc[(r0+8)*SCP + cb] = v2;
            v2.x = c1[0]*0.125f; v2.y = c1[1]*0.125f; *(float2*)&sc[r0*SCP + cb + 8] = v2;
            v2.x = c1[2]*0.125f; v2.y = c1[3]*0.125f; *(float2*)&sc[(r0+8)*SCP + cb + 8] = v2;
        }
    }

    int jmax = i0 + 32;
    auto loadV = [&](int jbase, int rows, int bf) {
        uint32_t VH = sb + AT_K + bf * AT_KSZ;
        int total = rows * 8;
#pragma unroll
        for (int u = 0; u < 4; u++) {
            int l = t + u * 512;
            if (l < total) {
                int row = l >> 3, ch = l & 7;
                const char* sh = (const char*)(vhi + base_k + (size_t)(jbase+row)*DD) + ch*16;
                CPASYNC16(VH + row*144 + ch*16, sh);
            }
        }
        CPCOMMIT();
    };

    // prefetch V tile 0 (hidden under row math)
    loadV(0, jmax < 256 ? jmax : 256, 0);
    __syncthreads();

    // ---- per-row math: lean, stores PACKED half2(hi,lo) unnormalized e2
    {
        float gamma = -log1pf(__expf(gammas[h]));
        for (int rr2 = 0; rr2 < 2; rr2++) {
            int r  = w*2 + rr2;
            int ig = i0 + r;
            float* row = sc + r*SCP;
            int cmask = ig >> 5;           // == i0/32 for all rows in tile

            // pass B: sums (predicate only at boundary chunk)
            float sum1 = 0.f, summ = 0.f;
            {
                const float* pr = row + lane;
                int c = 0;
                for (; c < cmask; c++) {
                    float p = __expf(pr[c*32]);
                    sum1 += p; summ += p;
                }
                {
                    int j = cmask*32 + lane;
                    float p = __expf(pr[cmask*32]);
                    sum1 += p;
                    if (j <= ig) summ += p;
                }
                for (c = cmask + 1; c < 32; c++)
                    sum1 += __expf(pr[c*32]);
            }
#pragma unroll
            for (int o = 16; o > 0; o >>= 1) {
                sum1 += __shfl_xor_sync(0xffffffffu, sum1, o);
                summ += __shfl_xor_sync(0xffffffffu, summ, o);
            }
            float inv1 = 1.f / sum1;

            // pass C: scan + decay + exp + sum2; store packed hi/lo, 2 chunks/iter
            float carry = 0.f, sum2 = 0.f;
            for (int c = 0; c <= cmask; c += 2) {
                int j0 = c*32 + lane;
                int j1 = j0 + 32;
                bool has1 = (c + 1 <= cmask);
                float s0 = row[j0];
                float s1v = has1 ? row[j1] : 0.f;
                float x0 = (j0 <= ig) ? __expf(s0) : 0.f;
                float x1 = (has1 && j1 <= ig) ? __expf(s1v) : 0.f;
#pragma unroll
                for (int o = 1; o < 32; o <<= 1) {
                    float y0 = __shfl_up_sync(0xffffffffu, x0, o);
                    float y1 = __shfl_up_sync(0xffffffffu, x1, o);
                    if (lane >= o) { x0 += y0; x1 += y1; }
                }
                float t0 = __shfl_sync(0xffffffffu, x0, 31);
                float t1 = __shfl_sync(0xffffffffu, x1, 31);
                float d0 = carry + x0;
                float d1 = carry + t0 + x1;
                carry += t0 + t1;
                {
                    float pos  = fabsf((float)(ig - j0));
                    float dd   = (summ - d0) * inv1 * pos;
                    float dist = sqrtf(fmaxf(dd, 0.f));
                    float eff  = fminf(fmaxf(__expf(dist * gamma), 1e-5f), 1e5f);
                    float e2 = (j0 <= ig) ? __expf(s0 * eff) : 0.f;
                    sum2 += e2;
                    float hv = __half2float(__float2half_rn(e2));
                    row[j0] = __uint_as_float(packh2(e2, e2 - hv));
                }
                if (has1) {
                    float pos  = fabsf((float)(ig - j1));
                    float dd   = (summ - d1) * inv1 * pos;
                    float dist = sqrtf(fmaxf(dd, 0.f));
                    float eff  = fminf(fmaxf(__expf(dist * gamma), 1e-5f), 1e5f);
                    float e2 = (j1 <= ig) ? __expf(s1v * eff) : 0.f;
                    sum2 += e2;
                    float hv = __half2float(__float2half_rn(e2));
                    row[j1] = __uint_as_float(packh2(e2, e2 - hv));
                }
            }
#pragma unroll
            for (int o = 16; o > 0; o >>= 1) sum2 += __shfl_xor_sync(0xffffffffu, sum2, o);
            if (lane == 0) row[1024] = 1.f / sum2;   // per-row inv2 in pad slot
        }
    }

    // ---- PV: packed probs -> PRMT fragment build; normalize in epilogue
    float acc[4] = {0.f, 0.f, 0.f, 0.f};
    int rr = lane >> 2, kc = (lane & 3) * 2;
    int vrow = lane & 15;
    int ntiles = (jmax + 255) >> 8;
    for (int ji = 0; ji < ntiles; ji++) {
        int jbase = ji * 256;
        int rows = jmax - jbase; if (rows > 256) rows = 256;
        CPWAIT0();
        __syncthreads();
        if (ji + 1 < ntiles) {
            int nb = jbase + 256;
            int nrows = jmax - nb; if (nrows > 256) nrows = 256;
            loadV(nb, nrows, (ji + 1) & 1);
        }
        uint32_t VH = sb + AT_K + (ji & 1) * AT_KSZ;

        int nk = rows >> 4;
        for (int kk = 0; kk < nk; kk++) {
            int j0 = jbase + kk*16;
            uint32_t vh[2];
            uint32_t va = (uint32_t)(kk*16 + vrow)*144 + (uint32_t)cg*16;
            LDSM_X2T(vh, VH + va);
            const uint32_t* p0 = (const uint32_t*)&sc[(mt*16 + rr)*SCP + j0 + kc];
            uint32_t s00 = p0[0],       s01 = p0[1];
            uint32_t s10 = p0[8*SCP],   s11 = p0[8*SCP+1];
            uint32_t s20 = p0[8],       s21 = p0[9];
            uint32_t s30 = p0[8*SCP+8], s31 = p0[8*SCP+9];
            uint32_t a_h[4], a_l[4];
            a_h[0] = __byte_perm(s00, s01, 0x5410); a_l[0] = __byte_perm(s00, s01, 0x7632);
            a_h[1] = __byte_perm(s10, s11, 0x5410); a_l[1] = __byte_perm(s10, s11, 0x7632);
            a_h[2] = __byte_perm(s20, s21, 0x5410); a_l[2] = __byte_perm(s20, s21, 0x7632);
            a_h[3] = __byte_perm(s30, s31, 0x5410); a_l[3] = __byte_perm(s30, s31, 0x7632);
            mma_f16(acc, a_h, vh);
            mma_f16(acc, a_l, vh);
        }
    }

    // ---- epilogue: apply per-row inv2, emit concat single fp16
    {
        float inv2a = sc[(mt*16 + rr)*SCP + 1024];
        float inv2b = sc[(mt*16 + rr + 8)*SCP + 1024];
        size_t o0 = ((size_t)b*SS + i0 + mt*16 + rr)*DD + h*64 + cg*8 + kc;
        size_t o1 = o0 + (size_t)8*DD;
        *(uint32_t*)&ohi[o0] = packh2(acc[0]*inv2a, acc[1]*inv2a);
        *(uint32_t*)&ohi[o1] = packh2(acc[2]*inv2b, acc[3]*inv2b);
    }
}

// ---------------- residual add + LayerNorm ----------------------------------
template<bool SPLITOUT>
__global__ void __launch_bounds__(256) add_ln_kernel(
    const float* __restrict__ A, const float* __restrict__ Bres,
    const float* __restrict__ w, const float* __restrict__ bias,
    float* __restrict__ outp,
    __half* __restrict__ ohi)
{
    __shared__ float red1[8], red2[8];
    int row = blockIdx.x;
    int t   = threadIdx.x;
    const float* pa = A    + (size_t)row*DD;
    const float* pb = Bres + (size_t)row*DD;

    float4 a4 = *(const float4*)&pa[t*4];
    float4 b4 = *(const float4*)&pb[t*4];
    float v0 = a4.x + b4.x, v1 = a4.y + b4.y, v2 = a4.z + b4.z, v3 = a4.w + b4.w;

    int lane = t & 31, wp = t >> 5;
    float s = v0 + v1 + v2 + v3;
#pragma unroll
    for (int o = 16; o > 0; o >>= 1) s += __shfl_xor_sync(0xffffffffu, s, o);
    if (lane == 0) red1[wp] = s;
    __syncthreads();
    float tot = 0.f;
#pragma unroll
    for (int i = 0; i < 8; i++) tot += red1[i];
    float mu = tot * (1.f / DD);

    float d0 = v0-mu, d1 = v1-mu, d2 = v2-mu, d3 = v3-mu;
    float q2 = d0*d0 + d1*d1 + d2*d2 + d3*d3;
#pragma unroll
    for (int o = 16; o > 0; o >>= 1) q2 += __shfl_xor_sync(0xffffffffu, q2, o);
    if (lane == 0) red2[wp] = q2;
    __syncthreads();
    float tv = 0.f;
#pragma unroll
    for (int i = 0; i < 8; i++) tv += red2[i];
    float inv = rsqrtf(tv * (1.f / DD) + 1e-5f);

    float4 w4  = *(const float4*)&w[t*4];
    float4 bi4 = *(const float4*)&bias[t*4];
    float4 o4;
    o4.x = d0*inv*w4.x + bi4.x;
    o4.y = d1*inv*w4.y + bi4.y;
    o4.z = d2*inv*w4.z + bi4.z;
    o4.w = d3*inv*w4.w + bi4.w;
    *(float4*)&outp[(size_t)row*DD + t*4] = o4;

    if (SPLITOUT) {
        uint32_t h0 = packh2(o4.x, o4.y), h1 = packh2(o4.z, o4.w);
        size_t base2 = (size_t)row * (DD/2) + t*2;
        ((uint32_t*)ohi)[base2]     = h0;
        ((uint32_t*)ohi)[base2 + 1] = h1;
    }
}

// ---------------- launcher ---------------------------------------------------
extern "C" void kernel_launch(void* const* d_in, const int* in_sizes, int n_in,
                              void* d_out, int out_size)
{
    int off = (in_sizes[0] == 1) ? 1 : 0;
    const float* query  = (const float*)d_in[off + 0];
    const float* key    = (const float*)d_in[off + 1];
    const float* values = (const float*)d_in[off + 2];
    const float* Wq = (const float*)d_in[off + 3];
    const float* bq = (const float*)d_in[off + 4];
    const float* Wk = (const float*)d_in[off + 5];
    const float* bk = (const float*)d_in[off + 6];
    const float* Wv = (const float*)d_in[off + 7];
    const float* bv = (const float*)d_in[off + 8];
    const float* Wo = (const float*)d_in[off + 9];
    const float* bo = (const float*)d_in[off + 10];
    const float* gammas = (const float*)d_in[off + 11];
    const float* ln1w = (const float*)d_in[off + 12];
    const float* ln1b = (const float*)d_in[off + 13];
    const float* W1 = (const float*)d_in[off + 14];
    const float* b1 = (const float*)d_in[off + 15];
    const float* W2 = (const float*)d_in[off + 16];
    const float* b2 = (const float*)d_in[off + 17];
    const float* ln2w = (const float*)d_in[off + 18];
    const float* ln2b = (const float*)d_in[off + 19];

    float *pattnout, *px, *pf;
    cudaGetSymbolAddress((void**)&pattnout, g_attnout);
    cudaGetSymbolAddress((void**)&px, g_x);
    cudaGetSymbolAddress((void**)&pf, g_f);

    __half *aq,*ak,*av;
    __half *wqh,*wkh,*wvh,*woh,*w1h,*w2h;
    __half *chi,*xh,*hh,*qhi,*qlo,*khi,*vhi;
    cudaGetSymbolAddress((void**)&aq, g_aq);
    cudaGetSymbolAddress((void**)&ak, g_ak);
    cudaGetSymbolAddress((void**)&av, g_av);
    cudaGetSymbolAddress((void**)&wqh, g_wq_h);
    cudaGetSymbolAddress((void**)&wkh, g_wk_h);
    cudaGetSymbolAddress((void**)&wvh, g_wv_h);
    cudaGetSymbolAddress((void**)&woh, g_wo_h);
    cudaGetSymbolAddress((void**)&w1h, g_w1_h);
    cudaGetSymbolAddress((void**)&w2h, g_w2_h);
    cudaGetSymbolAddress((void**)&chi, g_chi);
    cudaGetSymbolAddress((void**)&xh, g_xh);
    cudaGetSymbolAddress((void**)&hh, g_hh);
    cudaGetSymbolAddress((void**)&qhi, g_qhi);   cudaGetSymbolAddress((void**)&qlo, g_qlo);
    cudaGetSymbolAddress((void**)&khi, g_khi);
    cudaGetSymbolAddress((void**)&vhi, g_vhi);

    const int M = BB * SS;   // 4096
    cudaFuncSetAttribute(gemm_mma<false,false>, cudaFuncAttributeMaxDynamicSharedMemorySize, G_SMEM);
    cudaFuncSetAttribute(gemm_mma<false,true>,  cudaFuncAttributeMaxDynamicSharedMemorySize, G_SMEM);
    cudaFuncSetAttribute(gemm_mma<true,true>,   cudaFuncAttributeMaxDynamicSharedMemorySize, G_SMEM);
    cudaFuncSetAttribute(attn_kernel, cudaFuncAttributeMaxDynamicSharedMemorySize, AT_SMEM);

    // -------- #0: split A (QKV activations + QKV weights) --------
    {
        SplitArgs sa;
        const float* srcs[6] = {query, key, values, Wq, Wk, Wv};
        __half* his[6] = {aq, ak, av, wqh, wkh, wvh};
        int nblk[6] = {4096, 4096, 4096, 1024, 1024, 1024};
        int cum = 0;
        for (int i = 0; i < 6; i++) {
            sa.seg[i].src = srcs[i]; sa.seg[i].hi = his[i];
            sa.start[i] = cum; cum += nblk[i];
        }
        for (int i = 6; i < 9; i++) { sa.seg[i] = sa.seg[5]; sa.start[i] = cum; }
        sa.start[9] = cum;
        multi_split_kernel<<<cum, 256>>>(sa);
    }

    // -------- #1: QKV projections --------
    {
        GemmIO q = {aq, wqh, bq, nullptr, qhi, qlo};
        GemmIO k = {ak, wkh, bk, nullptr, khi, nullptr};
        GemmIO v = {av, wvh, bv, nullptr, vhi, nullptr};
        gemm_mma<false,true><<<dim3(DD/128, M/256, 3), 512, G_SMEM>>>(q, k, v, M, DD, DD);
    }

    // -------- #2: split B (Wo, W1, W2) --------
    {
        SplitArgs sa;
        const float* srcs[3] = {Wo, W1, W2};
        __half* his[3] = {woh, w1h, w2h};
        int nblk[3] = {1024, 4096, 4096};
        int cum = 0;
        for (int i = 0; i < 3; i++) {
            sa.seg[i].src = srcs[i]; sa.seg[i].hi = his[i];
            sa.start[i] = cum; cum += nblk[i];
        }
        for (int i = 3; i < 9; i++) { sa.seg[i] = sa.seg[2]; sa.start[i] = cum; }
        sa.start[9] = cum;
        multi_split_kernel<<<cum, 256>>>(sa);
    }

    // -------- #3: attention (profiled slot) --------
    attn_kernel<<<dim3(HH*BB, SS/32, 1), 512, AT_SMEM>>>(qhi, qlo, khi, vhi, gammas, chi);

    // -------- #4: output projection --------
    {
        GemmIO o = {chi, woh, bo, pattnout, nullptr, nullptr};
        gemm_mma<false,false><<<dim3(DD/128, M/256, 1), 512, G_SMEM>>>(o, o, o, M, DD, DD);
    }

    // -------- #5: LN1 --------
    add_ln_kernel<true><<<M, 256>>>(query, pattnout, ln1w, ln1b, px, xh);

    // -------- #6: FFN1 (+ReLU) --------
    {
        GemmIO f1 = {xh, w1h, b1, nullptr, hh, nullptr};
        gemm_mma<true,true><<<dim3(DFFF/128, M/256, 1), 512, G_SMEM>>>(f1, f1, f1, M, DFFF, DD);
    }

    // -------- #7: FFN2 --------
    {
        GemmIO f2 = {hh, w2h, b2, pf, nullptr, nullptr};
        gemm_mma<false,false><<<dim3(DD/128, M/256, 1), 512, G_SMEM>>>(f2, f2, f2, M, DD, DFFF);
    }

    // -------- #8: LN2 --------
    add_ln_kernel<false><<<M, 256>>>(px, pf, ln2w, ln2b, (float*)d_out, nullptr);
}

// round 17
// speedup vs baseline: 1.1094x; 1.0344x over previous
#include <cuda_runtime.h>
#include <cuda_fp16.h>
#include <math.h>
#include <stdint.h>

// Problem constants
#define BB 4
#define SS 1024
#define DD 1024
#define HH 16
#define DKK 64
#define DFFF 4096
#define SCP 1032   // score row pitch (floats); slot [1024] holds per-row inv2

// ---------------- scratch (device globals) -----------------------------------
__device__ float g_attnout[BB*SS*DD];
__device__ float g_x[BB*SS*DD];
__device__ float g_f[BB*SS*DD];
__device__ __half g_aq[BB*SS*DD];
__device__ __half g_ak[BB*SS*DD];
__device__ __half g_av[BB*SS*DD];
__device__ __half g_wq_h[DD*DD];
__device__ __half g_wk_h[DD*DD];
__device__ __half g_wv_h[DD*DD];
__device__ __half g_wo_h[DD*DD];
__device__ __half g_w1_h[DFFF*DD];
__device__ __half g_w2_h[DD*DFFF];
__device__ __half g_chi[BB*SS*DD];
__device__ __half g_xh[BB*SS*DD];
__device__ __half g_hh[BB*SS*DFFF];
__device__ __half g_qhi[BB*SS*DD], g_qlo[BB*SS*DD];
__device__ __half g_khi[BB*SS*DD];
__device__ __half g_vhi[BB*SS*DD];

// ======================= PTX helpers ========================================
__device__ __forceinline__ uint32_t smem_u32(const void* p) {
    uint32_t a;
    asm("{ .reg .u64 t; cvta.to.shared.u64 t, %1; cvt.u32.u64 %0, t; }" : "=r"(a) : "l"(p));
    return a;
}

#define CPASYNC16(dst, src) asm volatile("cp.async.cg.shared.global [%0], [%1], 16;" :: "r"(dst), "l"(src) : "memory")
#define CPCOMMIT() asm volatile("cp.async.commit_group;" ::: "memory")
#define CPWAIT1()  asm volatile("cp.async.wait_group 1;" ::: "memory")
#define CPWAIT0()  asm volatile("cp.async.wait_group 0;" ::: "memory")

#define LDSM_X4(R, A) \
    asm volatile("ldmatrix.sync.aligned.m8n8.x4.shared.b16 {%0,%1,%2,%3}, [%4];" \
        : "=r"((R)[0]), "=r"((R)[1]), "=r"((R)[2]), "=r"((R)[3]) : "r"(A))

#define LDSM_X2T(R, A) \
    asm volatile("ldmatrix.sync.aligned.m8n8.x2.trans.shared.b16 {%0,%1}, [%2];" \
        : "=r"((R)[0]), "=r"((R)[1]) : "r"(A))

__device__ __forceinline__ void mma_f16(float* c, const uint32_t* a, const uint32_t* b) {
    asm volatile(
        "mma.sync.aligned.m16n8k16.row.col.f32.f16.f16.f32 "
        "{%0,%1,%2,%3}, {%4,%5,%6,%7}, {%8,%9}, {%0,%1,%2,%3};"
        : "+f"(c[0]), "+f"(c[1]), "+f"(c[2]), "+f"(c[3])
        : "r"(a[0]), "r"(a[1]), "r"(a[2]), "r"(a[3]), "r"(b[0]), "r"(b[1]));
}

__device__ __forceinline__ uint32_t packh2(float x, float y) {
    __half2 t = __floats2half2_rn(x, y);
    return *reinterpret_cast<uint32_t*>(&t);
}
__device__ __forceinline__ uint32_t packloh2(float x, float y, uint32_t hi) {
    __half2 h = *reinterpret_cast<__half2*>(&hi);
    return packh2(x - __half2float(h.x), y - __half2float(h.y));
}

// ================ mega split: fp32 -> single fp16 ===========================
struct SplitSeg { const float* src; __half* hi; };
struct SplitArgs { SplitSeg seg[9]; int start[10]; };

__global__ void __launch_bounds__(256) multi_split_kernel(SplitArgs a)
{
    int bx = blockIdx.x;
    int s = 0;
#pragma unroll
    for (int i = 0; i < 8; i++) if (bx >= a.start[i+1]) s = i+1;
    SplitSeg sg = a.seg[s];
    int i = (bx - a.start[s]) * 256 + threadIdx.x;
    float4 v = ((const float4*)sg.src)[i];
    uint32_t h0 = packh2(v.x, v.y), h1 = packh2(v.z, v.w);
    ((uint32_t*)sg.hi)[i*2+0] = h0;
    ((uint32_t*)sg.hi)[i*2+1] = h1;
}

// ====== fp16 GEMM: C = A @ W^T + bias, tile 256x128, K-chunk 64, 3 stages ===
#define G_BH 36864
#define G_STAGE 55296
#define G_SMEM (3 * G_STAGE)   // 165888

struct GemmIO {
    const __half *Ah, *Wh;
    const float* bias;
    float* C;
    __half *Chi, *Clo;
};

template<bool RELU, bool SPLITOUT>
__global__ void __launch_bounds__(512, 1) gemm_mma(
    GemmIO io0, GemmIO io1, GemmIO io2, int M, int N, int K)
{
    extern __shared__ __align__(128) char smem[];
    uint32_t sb = smem_u32(smem);

    GemmIO io = (blockIdx.z == 0) ? io0 : (blockIdx.z == 1) ? io1 : io2;

    int tid  = threadIdx.x;
    int lane = tid & 31;
    int wid  = tid >> 5;
    int wm   = wid & 3;
    int wn   = wid >> 2;
    int bm = blockIdx.y * 256;
    int bn = blockIdx.x * 128;

    const int nch = K >> 6;

    auto load_stage = [&](int c) {
        uint32_t st = sb + (c % 3) * G_STAGE;
        size_t kof = (size_t)c * 64;
        const __half* a_h = io.Ah + (size_t)bm * K + kof;
        const __half* b_h = io.Wh + (size_t)bn * K + kof;
#pragma unroll
        for (int u = 0; u < 4; u++) {
            int l = tid + u * 512;
            int row = l >> 3, ch = l & 7;
            CPASYNC16(st + row*144 + ch*16, (const char*)(a_h + (size_t)row*K) + ch*16);
        }
#pragma unroll
        for (int u = 0; u < 2; u++) {
            int l = tid + u * 512;
            int row = l >> 3, ch = l & 7;
            CPASYNC16(st + G_BH + row*144 + ch*16, (const char*)(b_h + (size_t)row*K) + ch*16);
        }
        CPCOMMIT();
    };

    uint32_t aoff = ((((lane >> 3) & 1) * 8 + (lane & 7)) * 144) + (lane >> 4) * 16;
    uint32_t boff = (((lane >> 4) * 8 + (lane & 7)) * 144) + ((lane >> 3) & 1) * 16;

    float acc[4][4][4];
#pragma unroll
    for (int mt = 0; mt < 4; mt++)
#pragma unroll
        for (int n8 = 0; n8 < 4; n8++)
#pragma unroll
            for (int k = 0; k < 4; k++) acc[mt][n8][k] = 0.f;

    load_stage(0);
    load_stage(1);
    for (int c = 0; c < nch; c++) {
        if (c + 1 < nch) { CPWAIT1(); } else { CPWAIT0(); }
        __syncthreads();
        if (c + 2 < nch) load_stage(c + 2);

        uint32_t st = sb + (c % 3) * G_STAGE;
        uint32_t aH = st        + (wm * 64) * 144 + aoff;
        uint32_t bH = st + G_BH + (wn * 32) * 144 + boff;

#pragma unroll
        for (int ks = 0; ks < 4; ks++) {
            uint32_t ah[4][4];
#pragma unroll
            for (int mt = 0; mt < 4; mt++)
                LDSM_X4(ah[mt], aH + mt * (16*144) + ks * 32);
#pragma unroll
            for (int g = 0; g < 2; g++) {
                uint32_t bh[4];
                LDSM_X4(bh, bH + g * (16*144) + ks * 32);
#pragma unroll
                for (int mt = 0; mt < 4; mt++)
#pragma unroll
                    for (int hf = 0; hf < 2; hf++)
                        mma_f16(acc[mt][g*2+hf], ah[mt], &bh[hf*2]);
            }
        }
    }

    int r_in = lane >> 2;
    int c_in = (lane & 3) * 2;
    bool wlo = SPLITOUT && (io.Clo != nullptr);
#pragma unroll
    for (int mt = 0; mt < 4; mt++) {
        int R0 = bm + wm * 64 + mt * 16 + r_in;
        int R1 = R0 + 8;
#pragma unroll
        for (int n8 = 0; n8 < 4; n8++) {
            int col = bn + wn * 32 + n8 * 8 + c_in;
            float b0 = io.bias[col], b1 = io.bias[col + 1];
            float o00 = acc[mt][n8][0] + b0, o01 = acc[mt][n8][1] + b1;
            float o10 = acc[mt][n8][2] + b0, o11 = acc[mt][n8][3] + b1;
            if (RELU) {
                o00 = fmaxf(o00, 0.f); o01 = fmaxf(o01, 0.f);
                o10 = fmaxf(o10, 0.f); o11 = fmaxf(o11, 0.f);
            }
            if (SPLITOUT) {
                uint32_t h0 = packh2(o00, o01), h1 = packh2(o10, o11);
                *(uint32_t*)&io.Chi[(size_t)R0 * N + col] = h0;
                *(uint32_t*)&io.Chi[(size_t)R1 * N + col] = h1;
                if (wlo) {
                    uint32_t l0 = packloh2(o00, o01, h0), l1 = packloh2(o10, o11, h1);
                    *(uint32_t*)&io.Clo[(size_t)R0 * N + col] = l0;
                    *(uint32_t*)&io.Clo[(size_t)R1 * N + col] = l1;
                }
            } else {
                float2 o0, o1;
                o0.x = o00; o0.y = o01; o1.x = o10; o1.y = o11;
                *(float2*)&io.C[(size_t)R0 * N + col] = o0;
                *(float2*)&io.C[(size_t)R1 * N + col] = o1;
            }
        }
    }
}

// ================= tensor-core distance-decay attention ======================
// 512 threads, 32 rows/CTA, K/V tiles 256 rows. Grid (64, 32) wave-balanced.
// Row math: both warp rows INTERLEAVED x 2-chunk unroll = 4 independent scan
// chains per iteration (hides LDS/MUFU/SHFL latency at 1 CTA/SM occupancy).
#define AT_QH 132096
#define AT_QL 136704
#define AT_K  141312
#define AT_KSZ 36864
#define AT_SMEM 215040

__global__ void __launch_bounds__(512, 1) attn_kernel(
    const __half* __restrict__ qhi, const __half* __restrict__ qlo,
    const __half* __restrict__ khi, const __half* __restrict__ vhi,
    const float* __restrict__ gammas,
    __half* __restrict__ ohi)
{
    extern __shared__ __align__(128) char smx[];
    float* sc = (float*)smx;
    uint32_t sb = smem_u32(smx);
    const uint32_t QH = sb + AT_QH;
    const uint32_t QL = sb + AT_QL;

    int h = blockIdx.x & 15, b = blockIdx.x >> 4;
    int i0 = blockIdx.y * 32;
    int t = threadIdx.x, lane = t & 31, w = t >> 5;
    int mt = w & 1;
    int cg = w >> 1;

    size_t base_q = ((size_t)b*SS + i0)*DD + h*64;
    size_t base_k = (size_t)b*SS*DD + h*64;

    // ---- load Q tile (32 rows, hi+lo)
    {
        int sel = t >> 8;
        int idx = t & 255;
        int row = idx >> 3, ch = idx & 7;
        const __half* src = (sel ? qlo : qhi) + base_q + (size_t)row*DD + ch*8;
        char* dst = smx + (sel ? AT_QL : AT_QH) + row*144 + ch*16;
        *(float4*)dst = *(const float4*)src;
    }
    __syncthreads();

    uint32_t aoff = ((((lane >> 3) & 1) * 8 + (lane & 7)) * 144) + (lane >> 4) * 16;
    uint32_t boff = (((lane >> 4) * 8 + (lane & 7)) * 144) + ((lane >> 3) & 1) * 16;

    uint32_t ah[4][4], al[4][4];
#pragma unroll
    for (int ks = 0; ks < 4; ks++) {
        LDSM_X4(ah[ks], QH + mt*(16*144) + aoff + ks*32);
        LDSM_X4(al[ks], QL + mt*(16*144) + aoff + ks*32);
    }

    auto loadK = [&](int jt, int bf) {
        uint32_t KH = sb + AT_K + bf * AT_KSZ;
        int jbase = jt * 256;
#pragma unroll
        for (int u = 0; u < 4; u++) {
            int l = t + u * 512;
            int row = l >> 3, ch = l & 7;
            const char* sh = (const char*)(khi + base_k + (size_t)(jbase+row)*DD) + ch*16;
            CPASYNC16(KH + row*144 + ch*16, sh);
        }
        CPCOMMIT();
    };

    // ---- QK^T: 4 tiles of 256 cols, double-buffered
    loadK(0, 0);
    for (int jt = 0; jt < 4; jt++) {
        CPWAIT0();
        __syncthreads();
        if (jt + 1 < 4) loadK(jt + 1, (jt + 1) & 1);

        uint32_t KH = sb + AT_K + (jt & 1) * AT_KSZ;
#pragma unroll
        for (int half = 0; half < 2; half++) {
            float c0[4] = {0,0,0,0}, c1[4] = {0,0,0,0};
            uint32_t bb = (uint32_t)(half*128 + cg*16)*144 + boff;
#pragma unroll
            for (int ks = 0; ks < 4; ks++) {
                uint32_t bh[4];
                LDSM_X4(bh, KH + bb + ks*32);
                mma_f16(c0, ah[ks], &bh[0]);
                mma_f16(c0, al[ks], &bh[0]);
                mma_f16(c1, ah[ks], &bh[2]);
                mma_f16(c1, al[ks], &bh[2]);
            }
            int r0 = mt*16 + (lane >> 2);
            int cb = jt*256 + half*128 + cg*16 + (lane & 3)*2;
            float2 v2;
            v2.x = c0[0]*0.125f; v2.y = c0[1]*0.125f; *(float2*)&sc[r0*SCP + cb] = v2;
            v2.x = c0[2]*0.125f; v2.y = c0[3]*0.125f; *(float2*)&sc[(r0+8)*SCP + cb] = v2;
            v2.x = c1[0]*0.125f; v2.y = c1[1]*0.125f; *(float2*)&sc[r0*SCP + cb + 8] = v2;
            v2.x = c1[2]*0.125f; v2.y = c1[3]*0.125f; *(float2*)&sc[(r0+8)*SCP + cb + 8] = v2;
        }
    }

    int jmax = i0 + 32;
    auto loadV = [&](int jbase, int rows, int bf) {
        uint32_t VH = sb + AT_K + bf * AT_KSZ;
        int total = rows * 8;
#pragma unroll
        for (int u = 0; u < 4; u++) {
            int l = t + u * 512;
            if (l < total) {
                int row = l >> 3, ch = l & 7;
                const char* sh = (const char*)(vhi + base_k + (size_t)(jbase+row)*DD) + ch*16;
                CPASYNC16(VH + row*144 + ch*16, sh);
            }
        }
        CPCOMMIT();
    };

    // prefetch V tile 0 (hidden under row math)
    loadV(0, jmax < 256 ? jmax : 256, 0);
    __syncthreads();

    // ---- per-row math: BOTH rows interleaved, 2-chunk unroll (4 chains)
    {
        float gamma = -log1pf(__expf(gammas[h]));
        int r0i = w*2, r1i = r0i + 1;
        int ig0 = i0 + r0i, ig1 = i0 + r1i;
        float* row0 = sc + r0i*SCP;
        float* row1 = sc + r1i*SCP;
        int cmask = i0 >> 5;          // same for both rows (i0 32-aligned)

        // pass B: sums for both rows (2 streams)
        float sA = 0.f, mA = 0.f, sB = 0.f, mB = 0.f;
        {
            const float* p0 = row0 + lane;
            const float* p1 = row1 + lane;
            int c = 0;
            for (; c < cmask; c++) {
                float pa = __expf(p0[c*32]);
                float pb = __expf(p1[c*32]);
                sA += pa; mA += pa;
                sB += pb; mB += pb;
            }
            {
                int j = cmask*32 + lane;
                float pa = __expf(p0[cmask*32]);
                float pb = __expf(p1[cmask*32]);
                sA += pa; if (j <= ig0) mA += pa;
                sB += pb; if (j <= ig1) mB += pb;
            }
            for (c = cmask + 1; c < 32; c++) {
                sA += __expf(p0[c*32]);
                sB += __expf(p1[c*32]);
            }
        }
#pragma unroll
        for (int o = 16; o > 0; o >>= 1) {
            sA += __shfl_xor_sync(0xffffffffu, sA, o);
            mA += __shfl_xor_sync(0xffffffffu, mA, o);
            sB += __shfl_xor_sync(0xffffffffu, sB, o);
            mB += __shfl_xor_sync(0xffffffffu, mB, o);
        }
        float invA = 1.f / sA, invB = 1.f / sB;

        // pass C: 4 independent scan chains per iteration
        float carA = 0.f, carB = 0.f, s2A = 0.f, s2B = 0.f;
        for (int c = 0; c <= cmask; c += 2) {
            int j0 = c*32 + lane;
            int j1 = j0 + 32;
            bool has1 = (c + 1 <= cmask);
            float sa0 = row0[j0], sb0 = row1[j0];
            float sa1 = has1 ? row0[j1] : 0.f;
            float sb1 = has1 ? row1[j1] : 0.f;
            float xa0 = (j0 <= ig0) ? __expf(sa0) : 0.f;
            float xb0 = (j0 <= ig1) ? __expf(sb0) : 0.f;
            float xa1 = (has1 && j1 <= ig0) ? __expf(sa1) : 0.f;
            float xb1 = (has1 && j1 <= ig1) ? __expf(sb1) : 0.f;
#pragma unroll
            for (int o = 1; o < 32; o <<= 1) {
                float ya0 = __shfl_up_sync(0xffffffffu, xa0, o);
                float yb0 = __shfl_up_sync(0xffffffffu, xb0, o);
                float ya1 = __shfl_up_sync(0xffffffffu, xa1, o);
                float yb1 = __shfl_up_sync(0xffffffffu, xb1, o);
                if (lane >= o) { xa0 += ya0; xb0 += yb0; xa1 += ya1; xb1 += yb1; }
            }
            float ta0 = __shfl_sync(0xffffffffu, xa0, 31);
            float tb0 = __shfl_sync(0xffffffffu, xb0, 31);
            float ta1 = __shfl_sync(0xffffffffu, xa1, 31);
            float tb1 = __shfl_sync(0xffffffffu, xb1, 31);
            float da0 = carA + xa0;
            float da1 = carA + ta0 + xa1;
            carA += ta0 + ta1;
            float db0 = carB + xb0;
            float db1 = carB + tb0 + xb1;
            carB += tb0 + tb1;
            {   // row0, chunk c
                float pos  = fabsf((float)(ig0 - j0));
                float dd   = (mA - da0) * invA * pos;
                float eff  = fminf(fmaxf(__expf(sqrtf(fmaxf(dd, 0.f)) * gamma), 1e-5f), 1e5f);
                float e2 = (j0 <= ig0) ? __expf(sa0 * eff) : 0.f;
                s2A += e2;
                float hv = __half2float(__float2half_rn(e2));
                row0[j0] = __uint_as_float(packh2(e2, e2 - hv));
            }
            {   // row1, chunk c
                float pos  = fabsf((float)(ig1 - j0));
                float dd   = (mB - db0) * invB * pos;
                float eff  = fminf(fmaxf(__expf(sqrtf(fmaxf(dd, 0.f)) * gamma), 1e-5f), 1e5f);
                float e2 = (j0 <= ig1) ? __expf(sb0 * eff) : 0.f;
                s2B += e2;
                float hv = __half2float(__float2half_rn(e2));
                row1[j0] = __uint_as_float(packh2(e2, e2 - hv));
            }
            if (has1) {
                {   // row0, chunk c+1
                    float pos  = fabsf((float)(ig0 - j1));
                    float dd   = (mA - da1) * invA * pos;
                    float eff  = fminf(fmaxf(__expf(sqrtf(fmaxf(dd, 0.f)) * gamma), 1e-5f), 1e5f);
                    float e2 = (j1 <= ig0) ? __expf(sa1 * eff) : 0.f;
                    s2A += e2;
                    float hv = __half2float(__float2half_rn(e2));
                    row0[j1] = __uint_as_float(packh2(e2, e2 - hv));
                }
                {   // row1, chunk c+1
                    float pos  = fabsf((float)(ig1 - j1));
                    float dd   = (mB - db1) * invB * pos;
                    float eff  = fminf(fmaxf(__expf(sqrtf(fmaxf(dd, 0.f)) * gamma), 1e-5f), 1e5f);
                    float e2 = (j1 <= ig1) ? __expf(sb1 * eff) : 0.f;
                    s2B += e2;
                    float hv = __half2float(__float2half_rn(e2));
                    row1[j1] = __uint_as_float(packh2(e2, e2 - hv));
                }
            }
        }
#pragma unroll
        for (int o = 16; o > 0; o >>= 1) {
            s2A += __shfl_xor_sync(0xffffffffu, s2A, o);
            s2B += __shfl_xor_sync(0xffffffffu, s2B, o);
        }
        if (lane == 0) {
            row0[1024] = 1.f / s2A;
            row1[1024] = 1.f / s2B;
        }
    }

    // ---- PV: packed probs -> PRMT fragment build; normalize in epilogue
    float acc[4] = {0.f, 0.f, 0.f, 0.f};
    int rr = lane >> 2, kc = (lane & 3) * 2;
    int vrow = lane & 15;
    int ntiles = (jmax + 255) >> 8;
    for (int ji = 0; ji < ntiles; ji++) {
        int jbase = ji * 256;
        int rows = jmax - jbase; if (rows > 256) rows = 256;
        CPWAIT0();
        __syncthreads();
        if (ji + 1 < ntiles) {
            int nb = jbase + 256;
            int nrows = jmax - nb; if (nrows > 256) nrows = 256;
            loadV(nb, nrows, (ji + 1) & 1);
        }
        uint32_t VH = sb + AT_K + (ji & 1) * AT_KSZ;

        int nk = rows >> 4;
        for (int kk = 0; kk < nk; kk++) {
            int j0 = jbase + kk*16;
            uint32_t vh[2];
            uint32_t va = (uint32_t)(kk*16 + vrow)*144 + (uint32_t)cg*16;
            LDSM_X2T(vh, VH + va);
            const uint32_t* p0 = (const uint32_t*)&sc[(mt*16 + rr)*SCP + j0 + kc];
            uint32_t s00 = p0[0],       s01 = p0[1];
            uint32_t s10 = p0[8*SCP],   s11 = p0[8*SCP+1];
            uint32_t s20 = p0[8],       s21 = p0[9];
            uint32_t s30 = p0[8*SCP+8], s31 = p0[8*SCP+9];
            uint32_t a_h[4], a_l[4];
            a_h[0] = __byte_perm(s00, s01, 0x5410); a_l[0] = __byte_perm(s00, s01, 0x7632);
            a_h[1] = __byte_perm(s10, s11, 0x5410); a_l[1] = __byte_perm(s10, s11, 0x7632);
            a_h[2] = __byte_perm(s20, s21, 0x5410); a_l[2] = __byte_perm(s20, s21, 0x7632);
            a_h[3] = __byte_perm(s30, s31, 0x5410); a_l[3] = __byte_perm(s30, s31, 0x7632);
            mma_f16(acc, a_h, vh);
            mma_f16(acc, a_l, vh);
        }
    }

    // ---- epilogue: apply per-row inv2, emit concat single fp16
    {
        float inv2a = sc[(mt*16 + rr)*SCP + 1024];
        float inv2b = sc[(mt*16 + rr + 8)*SCP + 1024];
        size_t o0 = ((size_t)b*SS + i0 + mt*16 + rr)*DD + h*64 + cg*8 + kc;
        size_t o1 = o0 + (size_t)8*DD;
        *(uint32_t*)&ohi[o0] = packh2(acc[0]*inv2a, acc[1]*inv2a);
        *(uint32_t*)&ohi[o1] = packh2(acc[2]*inv2b, acc[3]*inv2b);
    }
}

// ---------------- residual add + LayerNorm ----------------------------------
template<bool SPLITOUT>
__global__ void __launch_bounds__(256) add_ln_kernel(
    const float* __restrict__ A, const float* __restrict__ Bres,
    const float* __restrict__ w, const float* __restrict__ bias,
    float* __restrict__ outp,
    __half* __restrict__ ohi)
{
    __shared__ float red1[8], red2[8];
    int row = blockIdx.x;
    int t   = threadIdx.x;
    const float* pa = A    + (size_t)row*DD;
    const float* pb = Bres + (size_t)row*DD;

    float4 a4 = *(const float4*)&pa[t*4];
    float4 b4 = *(const float4*)&pb[t*4];
    float v0 = a4.x + b4.x, v1 = a4.y + b4.y, v2 = a4.z + b4.z, v3 = a4.w + b4.w;

    int lane = t & 31, wp = t >> 5;
    float s = v0 + v1 + v2 + v3;
#pragma unroll
    for (int o = 16; o > 0; o >>= 1) s += __shfl_xor_sync(0xffffffffu, s, o);
    if (lane == 0) red1[wp] = s;
    __syncthreads();
    float tot = 0.f;
#pragma unroll
    for (int i = 0; i < 8; i++) tot += red1[i];
    float mu = tot * (1.f / DD);

    float d0 = v0-mu, d1 = v1-mu, d2 = v2-mu, d3 = v3-mu;
    float q2 = d0*d0 + d1*d1 + d2*d2 + d3*d3;
#pragma unroll
    for (int o = 16; o > 0; o >>= 1) q2 += __shfl_xor_sync(0xffffffffu, q2, o);
    if (lane == 0) red2[wp] = q2;
    __syncthreads();
    float tv = 0.f;
#pragma unroll
    for (int i = 0; i < 8; i++) tv += red2[i];
    float inv = rsqrtf(tv * (1.f / DD) + 1e-5f);

    float4 w4  = *(const float4*)&w[t*4];
    float4 bi4 = *(const float4*)&bias[t*4];
    float4 o4;
    o4.x = d0*inv*w4.x + bi4.x;
    o4.y = d1*inv*w4.y + bi4.y;
    o4.z = d2*inv*w4.z + bi4.z;
    o4.w = d3*inv*w4.w + bi4.w;
    *(float4*)&outp[(size_t)row*DD + t*4] = o4;

    if (SPLITOUT) {
        uint32_t h0 = packh2(o4.x, o4.y), h1 = packh2(o4.z, o4.w);
        size_t base2 = (size_t)row * (DD/2) + t*2;
        ((uint32_t*)ohi)[base2]     = h0;
        ((uint32_t*)ohi)[base2 + 1] = h1;
    }
}

// ---------------- launcher ---------------------------------------------------
extern "C" void kernel_launch(void* const* d_in, const int* in_sizes, int n_in,
                              void* d_out, int out_size)
{
    int off = (in_sizes[0] == 1) ? 1 : 0;
    const float* query  = (const float*)d_in[off + 0];
    const float* key    = (const float*)d_in[off + 1];
    const float* values = (const float*)d_in[off + 2];
    const float* Wq = (const float*)d_in[off + 3];
    const float* bq = (const float*)d_in[off + 4];
    const float* Wk = (const float*)d_in[off + 5];
    const float* bk = (const float*)d_in[off + 6];
    const float* Wv = (const float*)d_in[off + 7];
    const float* bv = (const float*)d_in[off + 8];
    const float* Wo = (const float*)d_in[off + 9];
    const float* bo = (const float*)d_in[off + 10];
    const float* gammas = (const float*)d_in[off + 11];
    const float* ln1w = (const float*)d_in[off + 12];
    const float* ln1b = (const float*)d_in[off + 13];
    const float* W1 = (const float*)d_in[off + 14];
    const float* b1 = (const float*)d_in[off + 15];
    const float* W2 = (const float*)d_in[off + 16];
    const float* b2 = (const float*)d_in[off + 17];
    const float* ln2w = (const float*)d_in[off + 18];
    const float* ln2b = (const float*)d_in[off + 19];

    float *pattnout, *px, *pf;
    cudaGetSymbolAddress((void**)&pattnout, g_attnout);
    cudaGetSymbolAddress((void**)&px, g_x);
    cudaGetSymbolAddress((void**)&pf, g_f);

    __half *aq,*ak,*av;
    __half *wqh,*wkh,*wvh,*woh,*w1h,*w2h;
    __half *chi,*xh,*hh,*qhi,*qlo,*khi,*vhi;
    cudaGetSymbolAddress((void**)&aq, g_aq);
    cudaGetSymbolAddress((void**)&ak, g_ak);
    cudaGetSymbolAddress((void**)&av, g_av);
    cudaGetSymbolAddress((void**)&wqh, g_wq_h);
    cudaGetSymbolAddress((void**)&wkh, g_wk_h);
    cudaGetSymbolAddress((void**)&wvh, g_wv_h);
    cudaGetSymbolAddress((void**)&woh, g_wo_h);
    cudaGetSymbolAddress((void**)&w1h, g_w1_h);
    cudaGetSymbolAddress((void**)&w2h, g_w2_h);
    cudaGetSymbolAddress((void**)&chi, g_chi);
    cudaGetSymbolAddress((void**)&xh, g_xh);
    cudaGetSymbolAddress((void**)&hh, g_hh);
    cudaGetSymbolAddress((void**)&qhi, g_qhi);   cudaGetSymbolAddress((void**)&qlo, g_qlo);
    cudaGetSymbolAddress((void**)&khi, g_khi);
    cudaGetSymbolAddress((void**)&vhi, g_vhi);

    const int M = BB * SS;   // 4096
    cudaFuncSetAttribute(gemm_mma<false,false>, cudaFuncAttributeMaxDynamicSharedMemorySize, G_SMEM);
    cudaFuncSetAttribute(gemm_mma<false,true>,  cudaFuncAttributeMaxDynamicSharedMemorySize, G_SMEM);
    cudaFuncSetAttribute(gemm_mma<true,true>,   cudaFuncAttributeMaxDynamicSharedMemorySize, G_SMEM);
    cudaFuncSetAttribute(attn_kernel, cudaFuncAttributeMaxDynamicSharedMemorySize, AT_SMEM);

    // -------- #0: split A (QKV activations + QKV weights) --------
    {
        SplitArgs sa;
        const float* srcs[6] = {query, key, values, Wq, Wk, Wv};
        __half* his[6] = {aq, ak, av, wqh, wkh, wvh};
        int nblk[6] = {4096, 4096, 4096, 1024, 1024, 1024};
        int cum = 0;
        for (int i = 0; i < 6; i++) {
            sa.seg[i].src = srcs[i]; sa.seg[i].hi = his[i];
            sa.start[i] = cum; cum += nblk[i];
        }
        for (int i = 6; i < 9; i++) { sa.seg[i] = sa.seg[5]; sa.start[i] = cum; }
        sa.start[9] = cum;
        multi_split_kernel<<<cum, 256>>>(sa);
    }

    // -------- #1: QKV projections --------
    {
        GemmIO q = {aq, wqh, bq, nullptr, qhi, qlo};
        GemmIO k = {ak, wkh, bk, nullptr, khi, nullptr};
        GemmIO v = {av, wvh, bv, nullptr, vhi, nullptr};
        gemm_mma<false,true><<<dim3(DD/128, M/256, 3), 512, G_SMEM>>>(q, k, v, M, DD, DD);
    }

    // -------- #2: split B (Wo, W1, W2) --------
    {
        SplitArgs sa;
        const float* srcs[3] = {Wo, W1, W2};
        __half* his[3] = {woh, w1h, w2h};
        int nblk[3] = {1024, 4096, 4096};
        int cum = 0;
        for (int i = 0; i < 3; i++) {
            sa.seg[i].src = srcs[i]; sa.seg[i].hi = his[i];
            sa.start[i] = cum; cum += nblk[i];
        }
        for (int i = 3; i < 9; i++) { sa.seg[i] = sa.seg[2]; sa.start[i] = cum; }
        sa.start[9] = cum;
        multi_split_kernel<<<cum, 256>>>(sa);
    }

    // -------- #3: attention (profiled slot) --------
    attn_kernel<<<dim3(HH*BB, SS/32, 1), 512, AT_SMEM>>>(qhi, qlo, khi, vhi, gammas, chi);

    // -------- #4: output projection --------
    {
        GemmIO o = {chi, woh, bo, pattnout, nullptr, nullptr};
        gemm_mma<false,false><<<dim3(DD/128, M/256, 1), 512, G_SMEM>>>(o, o, o, M, DD, DD);
    }

    // -------- #5: LN1 --------
    add_ln_kernel<true><<<M, 256>>>(query, pattnout, ln1w, ln1b, px, xh);

    // -------- #6: FFN1 (+ReLU) --------
    {
        GemmIO f1 = {xh, w1h, b1, nullptr, hh, nullptr};
        gemm_mma<true,true><<<dim3(DFFF/128, M/256, 1), 512, G_SMEM>>>(f1, f1, f1, M, DFFF, DD);
    }

    // -------- #7: FFN2 --------
    {
        GemmIO f2 = {hh, w2h, b2, pf, nullptr, nullptr};
        gemm_mma<false,false><<<dim3(DD/128, M/256, 1), 512, G_SMEM>>>(f2, f2, f2, M, DD, DFFF);
    }

    // -------- #8: LN2 --------
    add_ln_kernel<false><<<M, 256>>>(px, pf, ln2w, ln2b, (float*)d_out, nullptr);
}